// round 1
// baseline (speedup 1.0000x reference)
#include <cuda_runtime.h>

#define NN 100000
#define NE 1600000
#define NG 128
#define HID 64

// ---------------- scratch (device globals: allocation-free) ----------------
__device__ int   g_deg[NN];
__device__ int   g_rowptr[NN + 1];
__device__ int   g_cursor[NN];
__device__ int   g_col[NE];
__device__ float g_h0[NN * HID];
__device__ float g_h1[NN * HID];
__device__ float g_pool[NG * 4 * HID];   // pooled per-layer h, [G][256]
__device__ int   g_cnt[NG];
__device__ float g_pooledT[HID * NG];    // JK output, transposed [c][g]

// ---------------- zero scratch that is accumulated into ----------------
__global__ void k_zero() {
    int i = blockIdx.x * blockDim.x + threadIdx.x;
    int stride = gridDim.x * blockDim.x;
    for (int j = i; j < NN; j += stride) g_deg[j] = 0;
    for (int j = i; j < NG * 4 * HID; j += stride) g_pool[j] = 0.0f;
    for (int j = i; j < NG; j += stride) g_cnt[j] = 0;
}

// ---------------- CSR build: histogram over dst ----------------
__global__ void k_hist(const int* __restrict__ ei) {
    int e = blockIdx.x * blockDim.x + threadIdx.x;
    if (e < NE) atomicAdd(&g_deg[ei[NE + e]], 1);
}

// nodes-per-graph histogram (warp-aggregated; batch is sorted)
__global__ void k_cnt(const int* __restrict__ batch) {
    int n = blockIdx.x * blockDim.x + threadIdx.x;
    unsigned am = __ballot_sync(0xffffffffu, n < NN);
    if (n < NN) {
        int g = batch[n];
        unsigned mask = __match_any_sync(am, g);
        int leader = __ffs(mask) - 1;
        if ((threadIdx.x & 31) == leader) atomicAdd(&g_cnt[g], __popc(mask));
    }
}

// single-block exclusive scan of g_deg -> g_rowptr (+ cursor copy)
__global__ __launch_bounds__(1024) void k_scan() {
    __shared__ int s[1024];
    const int R = (NN + 1023) / 1024;  // 98
    int tid = threadIdx.x;
    int base = tid * R;
    int local = 0;
    for (int i = 0; i < R; i++) {
        int idx = base + i;
        if (idx < NN) local += g_deg[idx];
    }
    s[tid] = local;
    __syncthreads();
    for (int off = 1; off < 1024; off <<= 1) {
        int v = (tid >= off) ? s[tid - off] : 0;
        __syncthreads();
        s[tid] += v;
        __syncthreads();
    }
    int run = s[tid] - local;  // exclusive prefix for this thread's range
    for (int i = 0; i < R; i++) {
        int idx = base + i;
        if (idx < NN) {
            g_rowptr[idx] = run;
            g_cursor[idx] = run;
            run += g_deg[idx];
        }
    }
    if (tid == 1023) g_rowptr[NN] = s[1023];
}

// fill CSR col (src indices) keyed by dst
__global__ void k_fill(const int* __restrict__ ei) {
    int e = blockIdx.x * blockDim.x + threadIdx.x;
    if (e < NE) {
        int d = ei[NE + e];
        int slot = atomicAdd(&g_cursor[d], 1);
        g_col[slot] = ei[e];
    }
}

// ---------------- fused GIN layer: aggregate + MLP(2 stage) + relu ----------------
// block = 256 threads, node tile of 32. Warp-per-node gather; register-tiled GEMM.
template <int CIN>
__global__ __launch_bounds__(256) void k_gin(const float* __restrict__ hin,
                                             const float* __restrict__ W1,
                                             const float* __restrict__ b1,
                                             const float* __restrict__ W2,
                                             const float* __restrict__ b2,
                                             float* __restrict__ hout) {
    constexpr int CINP = CIN + 4;  // pad to de-conflict z column reads
    extern __shared__ float sm[];
    float* W1s = sm;                  // CIN*64
    float* W2s = W1s + CIN * 64;      // 64*64
    float* b1s = W2s + 4096;          // 64
    float* b2s = b1s + 64;            // 64
    float* zsh = b2s + 64;            // 32*CINP
    float* tsh = zsh + 32 * CINP;     // 32*68

    int tid = threadIdx.x;
    for (int i = tid; i < CIN * 64; i += 256) W1s[i] = W1[i];
    for (int i = tid; i < 4096; i += 256) W2s[i] = W2[i];
    if (tid < 64) { b1s[tid] = b1[tid]; b2s[tid] = b2[tid]; }

    const int warp = tid >> 5, lane = tid & 31;
    const int ty = tid >> 4, tx = tid & 15;
    const int m0 = ty * 2, c0 = tx * 4;
    const int nTiles = (NN + 31) / 32;

    for (int tile = blockIdx.x; tile < nTiles; tile += gridDim.x) {
        __syncthreads();  // protect zsh/tsh from previous iteration's readers

        // ---- Phase A: aggregation (z = h + sum_{src in row(n)} h[src]) ----
        for (int s = 0; s < 4; s++) {
            int m = warp * 4 + s;
            int n = tile * 32 + m;
            if (n < NN) {
                int rs = g_rowptr[n];
                int re = g_rowptr[n + 1];
                if (CIN == 128) {
                    const float4* __restrict__ hin4 = (const float4*)hin;
                    float4 acc = hin4[n * 32 + lane];  // self term
                    for (int j0 = rs; j0 < re; j0 += 32) {
                        int myc = (j0 + lane < re) ? g_col[j0 + lane] : 0;
                        int cnt = min(32, re - j0);
                        int jj = 0;
                        for (; jj + 4 <= cnt; jj += 4) {
                            int s0 = __shfl_sync(0xffffffffu, myc, jj);
                            int s1 = __shfl_sync(0xffffffffu, myc, jj + 1);
                            int s2 = __shfl_sync(0xffffffffu, myc, jj + 2);
                            int s3 = __shfl_sync(0xffffffffu, myc, jj + 3);
                            float4 v0 = hin4[s0 * 32 + lane];
                            float4 v1 = hin4[s1 * 32 + lane];
                            float4 v2 = hin4[s2 * 32 + lane];
                            float4 v3 = hin4[s3 * 32 + lane];
                            acc.x += (v0.x + v1.x) + (v2.x + v3.x);
                            acc.y += (v0.y + v1.y) + (v2.y + v3.y);
                            acc.z += (v0.z + v1.z) + (v2.z + v3.z);
                            acc.w += (v0.w + v1.w) + (v2.w + v3.w);
                        }
                        for (; jj < cnt; jj++) {
                            int sj = __shfl_sync(0xffffffffu, myc, jj);
                            float4 v = hin4[sj * 32 + lane];
                            acc.x += v.x; acc.y += v.y; acc.z += v.z; acc.w += v.w;
                        }
                    }
                    *(float4*)&zsh[m * CINP + 4 * lane] = acc;
                } else {
                    const float2* __restrict__ hin2 = (const float2*)hin;
                    float2 acc = hin2[n * 32 + lane];
                    for (int j0 = rs; j0 < re; j0 += 32) {
                        int myc = (j0 + lane < re) ? g_col[j0 + lane] : 0;
                        int cnt = min(32, re - j0);
                        int jj = 0;
                        for (; jj + 4 <= cnt; jj += 4) {
                            int s0 = __shfl_sync(0xffffffffu, myc, jj);
                            int s1 = __shfl_sync(0xffffffffu, myc, jj + 1);
                            int s2 = __shfl_sync(0xffffffffu, myc, jj + 2);
                            int s3 = __shfl_sync(0xffffffffu, myc, jj + 3);
                            float2 v0 = hin2[s0 * 32 + lane];
                            float2 v1 = hin2[s1 * 32 + lane];
                            float2 v2 = hin2[s2 * 32 + lane];
                            float2 v3 = hin2[s3 * 32 + lane];
                            acc.x += (v0.x + v1.x) + (v2.x + v3.x);
                            acc.y += (v0.y + v1.y) + (v2.y + v3.y);
                        }
                        for (; jj < cnt; jj++) {
                            int sj = __shfl_sync(0xffffffffu, myc, jj);
                            float2 v = hin2[sj * 32 + lane];
                            acc.x += v.x; acc.y += v.y;
                        }
                    }
                    *(float2*)&zsh[m * CINP + 2 * lane] = acc;
                }
            } else {
                if (CIN == 128)
                    *(float4*)&zsh[m * CINP + 4 * lane] = make_float4(0.f, 0.f, 0.f, 0.f);
                else
                    *(float2*)&zsh[m * CINP + 2 * lane] = make_float2(0.f, 0.f);
            }
        }
        __syncthreads();

        // ---- Phase B1: t = relu(z @ W1 + b1), [32 x 64] ----
        {
            float4 a0 = *(const float4*)&b1s[c0];
            float4 a1 = a0;
#pragma unroll 8
            for (int k = 0; k < CIN; k++) {
                float4 w = *(const float4*)&W1s[k * 64 + c0];
                float z0 = zsh[(m0 + 0) * CINP + k];
                float z1 = zsh[(m0 + 1) * CINP + k];
                a0.x += z0 * w.x; a0.y += z0 * w.y; a0.z += z0 * w.z; a0.w += z0 * w.w;
                a1.x += z1 * w.x; a1.y += z1 * w.y; a1.z += z1 * w.z; a1.w += z1 * w.w;
            }
            a0.x = fmaxf(a0.x, 0.f); a0.y = fmaxf(a0.y, 0.f);
            a0.z = fmaxf(a0.z, 0.f); a0.w = fmaxf(a0.w, 0.f);
            a1.x = fmaxf(a1.x, 0.f); a1.y = fmaxf(a1.y, 0.f);
            a1.z = fmaxf(a1.z, 0.f); a1.w = fmaxf(a1.w, 0.f);
            *(float4*)&tsh[(m0 + 0) * 68 + c0] = a0;
            *(float4*)&tsh[(m0 + 1) * 68 + c0] = a1;
        }
        __syncthreads();

        // ---- Phase B2: h = relu(t @ W2 + b2) ----
        {
            float4 o0 = *(const float4*)&b2s[c0];
            float4 o1 = o0;
#pragma unroll 8
            for (int k = 0; k < 64; k++) {
                float4 w = *(const float4*)&W2s[k * 64 + c0];
                float t0 = tsh[(m0 + 0) * 68 + k];
                float t1 = tsh[(m0 + 1) * 68 + k];
                o0.x += t0 * w.x; o0.y += t0 * w.y; o0.z += t0 * w.z; o0.w += t0 * w.w;
                o1.x += t1 * w.x; o1.y += t1 * w.y; o1.z += t1 * w.z; o1.w += t1 * w.w;
            }
            o0.x = fmaxf(o0.x, 0.f); o0.y = fmaxf(o0.y, 0.f);
            o0.z = fmaxf(o0.z, 0.f); o0.w = fmaxf(o0.w, 0.f);
            o1.x = fmaxf(o1.x, 0.f); o1.y = fmaxf(o1.y, 0.f);
            o1.z = fmaxf(o1.z, 0.f); o1.w = fmaxf(o1.w, 0.f);
            int n0 = tile * 32 + m0;
            if (n0 < NN)     *(float4*)&hout[n0 * 64 + c0] = o0;
            if (n0 + 1 < NN) *(float4*)&hout[(n0 + 1) * 64 + c0] = o1;
        }
    }
}

// ---------------- per-layer global-add-pool into g_pool[:, loff:loff+64] ----------------
// batch is sorted: accumulate runs in registers, atomic-flush only at graph boundaries.
__global__ void k_pool(const float* __restrict__ h, const int* __restrict__ batch, int loff) {
    int c = threadIdx.x & 63;
    int s = threadIdx.x >> 6;
    int n0 = blockIdx.x * 256 + s * 64;
    float acc = 0.0f;
    int curg = -1;
    for (int i = 0; i < 64; i++) {
        int n = n0 + i;
        if (n >= NN) break;
        int g = batch[n];
        if (g != curg) {
            if (curg >= 0) atomicAdd(&g_pool[curg * 256 + loff + c], acc);
            acc = 0.0f;
            curg = g;
        }
        acc += h[n * 64 + c];
    }
    if (curg >= 0) atomicAdd(&g_pool[curg * 256 + loff + c], acc);
}

// ---------------- JK projection at graph granularity ----------------
// pooled[g] = g_pool[g,:] @ Wjk + cnt[g] * bjk   (pool/Wjk linearity swap)
__global__ void k_jk(const float* __restrict__ Wjk, const float* __restrict__ bjk) {
    int g = blockIdx.x;
    int c = threadIdx.x;  // 64
    float acc = (float)g_cnt[g] * bjk[c];
#pragma unroll 4
    for (int k = 0; k < 256; k++) acc += g_pool[g * 256 + k] * Wjk[k * 64 + c];
    g_pooledT[c * NG + g] = acc;  // transposed for coalesced reads in k_final
}

// ---------------- classifier: Linear -> BN(batch stats) -> ReLU -> Linear ----------------
__global__ __launch_bounds__(128) void k_final(const float* __restrict__ Wc1,
                                               const float* __restrict__ bc1,
                                               const float* __restrict__ gamma,
                                               const float* __restrict__ beta,
                                               const float* __restrict__ Wc2,
                                               const float* __restrict__ bc2,
                                               float* __restrict__ out) {
    extern __shared__ float sm[];
    float* Wc1s = sm;                  // 4096
    float* zsh = Wc1s + 4096;          // 128*66
    float* scv = zsh + 128 * 66;       // 64
    float* shv = scv + 64;             // 64
    int tid = threadIdx.x;  // = graph index g
    for (int i = tid; i < 4096; i += 128) Wc1s[i] = Wc1[i];
    __syncthreads();

    // z[g,:] = pooled[g,:] @ Wc1 + bc1
    float4 acc4[16];
#pragma unroll
    for (int c = 0; c < 16; c++) acc4[c] = *(const float4*)&bc1[c * 4];
    for (int k = 0; k < 64; k++) {
        float pk = g_pooledT[k * NG + tid];
#pragma unroll
        for (int c = 0; c < 16; c++) {
            float4 w = *(const float4*)&Wc1s[k * 64 + c * 4];
            acc4[c].x += pk * w.x; acc4[c].y += pk * w.y;
            acc4[c].z += pk * w.z; acc4[c].w += pk * w.w;
        }
    }
#pragma unroll
    for (int c = 0; c < 16; c++) {
        zsh[tid * 66 + c * 4 + 0] = acc4[c].x;
        zsh[tid * 66 + c * 4 + 1] = acc4[c].y;
        zsh[tid * 66 + c * 4 + 2] = acc4[c].z;
        zsh[tid * 66 + c * 4 + 3] = acc4[c].w;
    }
    __syncthreads();

    // batch-norm statistics over the 128 graphs, per channel
    if (tid < 64) {
        float s = 0.f, s2 = 0.f;
        for (int g = 0; g < 128; g++) {
            float v = zsh[g * 66 + tid];
            s += v;
            s2 += v * v;
        }
        float mu = s * (1.0f / 128.0f);
        float var = s2 * (1.0f / 128.0f) - mu * mu;
        float sc = gamma[tid] * rsqrtf(var + 1e-5f);
        scv[tid] = sc;
        shv[tid] = beta[tid] - mu * sc;
    }
    __syncthreads();

    // out[g,:] = relu(norm(z[g,:])) @ Wc2 + bc2
    float ao[10];
#pragma unroll
    for (int o = 0; o < 10; o++) ao[o] = bc2[o];
    for (int c = 0; c < 64; c++) {
        float v = fmaxf(zsh[tid * 66 + c] * scv[c] + shv[c], 0.0f);
#pragma unroll
        for (int o = 0; o < 10; o++) ao[o] += v * Wc2[c * 10 + o];
    }
#pragma unroll
    for (int o = 0; o < 10; o++) out[tid * 10 + o] = ao[o];
}

// ---------------- launch ----------------
extern "C" void kernel_launch(void* const* d_in, const int* in_sizes, int n_in,
                              void* d_out, int out_size) {
    const float* x    = (const float*)d_in[0];
    const int*   ei   = (const int*)d_in[1];
    const int*   batch= (const int*)d_in[2];
    const float* W1f  = (const float*)d_in[3];
    const float* b1f  = (const float*)d_in[4];
    const float* W2f  = (const float*)d_in[5];
    const float* b2f  = (const float*)d_in[6];
    const float* W1r  = (const float*)d_in[7];
    const float* b1r  = (const float*)d_in[8];
    const float* W2r  = (const float*)d_in[9];
    const float* b2r  = (const float*)d_in[10];
    const float* Wjk  = (const float*)d_in[11];
    const float* bjk  = (const float*)d_in[12];
    const float* Wc1  = (const float*)d_in[13];
    const float* bc1  = (const float*)d_in[14];
    const float* gamma= (const float*)d_in[15];
    const float* beta = (const float*)d_in[16];
    const float* Wc2  = (const float*)d_in[17];
    const float* bc2  = (const float*)d_in[18];
    float* out = (float*)d_out;

    float *h0p = 0, *h1p = 0;
    cudaGetSymbolAddress((void**)&h0p, g_h0);
    cudaGetSymbolAddress((void**)&h1p, g_h1);

    const size_t sm0 = (size_t)(128 * 64 + 4096 + 128 + 32 * (128 + 4) + 32 * 68) * sizeof(float);
    const size_t smh = (size_t)(64 * 64 + 4096 + 128 + 32 * (64 + 4) + 32 * 68) * sizeof(float);
    const size_t smf = (size_t)(4096 + 128 * 66 + 128) * sizeof(float);
    cudaFuncSetAttribute(k_gin<128>, cudaFuncAttributeMaxDynamicSharedMemorySize, (int)sm0);
    cudaFuncSetAttribute(k_gin<64>,  cudaFuncAttributeMaxDynamicSharedMemorySize, (int)smh);
    cudaFuncSetAttribute(k_final,    cudaFuncAttributeMaxDynamicSharedMemorySize, (int)smf);

    // CSR build (reused by all 4 layers) + zeroed accumulators
    k_zero<<<256, 256>>>();
    k_hist<<<(NE + 255) / 256, 256>>>(ei);
    k_cnt<<<(NN + 255) / 256, 256>>>(batch);
    k_scan<<<1, 1024>>>();
    k_fill<<<(NE + 255) / 256, 256>>>(ei);

    const int POOL_GRID = (NN + 255) / 256;
    // layer 0 (128 -> 64)
    k_gin<128><<<444, 256, sm0>>>(x, W1f, b1f, W2f, b2f, h0p);
    k_pool<<<POOL_GRID, 256>>>(h0p, batch, 0);
    // layers 1..3 (64 -> 64), ping-pong h0/h1
    k_gin<64><<<592, 256, smh>>>(h0p, W1r, b1r, W2r, b2r, h1p);
    k_pool<<<POOL_GRID, 256>>>(h1p, batch, 64);
    k_gin<64><<<592, 256, smh>>>(h1p, W1r + 4096, b1r + 64, W2r + 4096, b2r + 64, h0p);
    k_pool<<<POOL_GRID, 256>>>(h0p, batch, 128);
    k_gin<64><<<592, 256, smh>>>(h0p, W1r + 2 * 4096, b1r + 2 * 64, W2r + 2 * 4096, b2r + 2 * 64, h1p);
    k_pool<<<POOL_GRID, 256>>>(h1p, batch, 192);

    // JK cat @ Wjk at graph granularity, then classifier + BN
    k_jk<<<NG, 64>>>(Wjk, bjk);
    k_final<<<1, 128, smf>>>(Wc1, bc1, gamma, beta, Wc2, bc2, out);
}

// round 2
// speedup vs baseline: 1.2201x; 1.2201x over previous
#include <cuda_runtime.h>

#define NN 100000
#define NE 1600000
#define NG 128
#define HID 64
#define NB 98   // ceil(NN / 1024)

// ---------------- scratch (device globals: allocation-free) ----------------
__device__ int   g_deg[NN];
__device__ int   g_rowptr[NN + 1];
__device__ int   g_cursor[NN];
__device__ int   g_col[NE];
__device__ int   g_bsum[NB];
__device__ float g_h0[NN * HID];
__device__ float g_h1[NN * HID];
__device__ float g_pool[NG * 4 * HID];   // pooled per-layer h, [G][256]
__device__ int   g_cnt[NG];
__device__ float g_pooledT[HID * NG];    // JK output, transposed [c][g]

// ---------------- zero scratch that is accumulated into ----------------
__global__ void k_zero() {
    int i = blockIdx.x * blockDim.x + threadIdx.x;
    int stride = gridDim.x * blockDim.x;
    for (int j = i; j < NN; j += stride) g_deg[j] = 0;
    for (int j = i; j < NG * 4 * HID; j += stride) g_pool[j] = 0.0f;
    for (int j = i; j < NG; j += stride) g_cnt[j] = 0;
}

// ---------------- CSR build: histogram over dst ----------------
__global__ void k_hist(const int* __restrict__ ei) {
    int e = blockIdx.x * blockDim.x + threadIdx.x;
    if (e < NE) atomicAdd(&g_deg[ei[NE + e]], 1);
}

// nodes-per-graph histogram (warp-aggregated; batch is sorted)
__global__ void k_cnt(const int* __restrict__ batch) {
    int n = blockIdx.x * blockDim.x + threadIdx.x;
    unsigned am = __ballot_sync(0xffffffffu, n < NN);
    if (n < NN) {
        int g = batch[n];
        unsigned mask = __match_any_sync(am, g);
        int leader = __ffs(mask) - 1;
        if ((threadIdx.x & 31) == leader) atomicAdd(&g_cnt[g], __popc(mask));
    }
}

// ---------------- multi-block exclusive scan of g_deg -> g_rowptr ----------------
// pass 1: per-block (1024-chunk) tree reduction -> g_bsum
__global__ __launch_bounds__(1024) void k_scan1() {
    __shared__ int s[1024];
    int t = threadIdx.x;
    int i = blockIdx.x * 1024 + t;
    s[t] = (i < NN) ? g_deg[i] : 0;
    __syncthreads();
#pragma unroll
    for (int off = 512; off > 0; off >>= 1) {
        if (t < off) s[t] += s[t + off];
        __syncthreads();
    }
    if (t == 0) g_bsum[blockIdx.x] = s[0];
}

// pass 2: single tiny block scans the 98 block sums (exclusive)
__global__ __launch_bounds__(128) void k_scan2() {
    __shared__ int s[128];
    int t = threadIdx.x;
    int v = (t < NB) ? g_bsum[t] : 0;
    s[t] = v;
    __syncthreads();
#pragma unroll
    for (int off = 1; off < 128; off <<= 1) {
        int u = (t >= off) ? s[t - off] : 0;
        __syncthreads();
        s[t] += u;
        __syncthreads();
    }
    if (t < NB) g_bsum[t] = s[t] - v;   // exclusive block offset
    if (t == 127) g_rowptr[NN] = s[127];  // total edge count
}

// pass 3: intra-block Hillis-Steele scan + block offset -> rowptr/cursor
__global__ __launch_bounds__(1024) void k_scan3() {
    __shared__ int s[1024];
    int t = threadIdx.x;
    int i = blockIdx.x * 1024 + t;
    int v = (i < NN) ? g_deg[i] : 0;
    s[t] = v;
    __syncthreads();
#pragma unroll
    for (int off = 1; off < 1024; off <<= 1) {
        int u = (t >= off) ? s[t - off] : 0;
        __syncthreads();
        s[t] += u;
        __syncthreads();
    }
    if (i < NN) {
        int ex = s[t] - v + g_bsum[blockIdx.x];
        g_rowptr[i] = ex;
        g_cursor[i] = ex;
    }
}

// fill CSR col (src indices) keyed by dst
__global__ void k_fill(const int* __restrict__ ei) {
    int e = blockIdx.x * blockDim.x + threadIdx.x;
    if (e < NE) {
        int d = ei[NE + e];
        int slot = atomicAdd(&g_cursor[d], 1);
        g_col[slot] = ei[e];
    }
}

// ---------------- fused GIN layer: aggregate + MLP(2 stage) + relu ----------------
// block = 256 threads, node tile of 32. Warp-per-node gather; register-tiled GEMM.
template <int CIN>
__global__ __launch_bounds__(256) void k_gin(const float* __restrict__ hin,
                                             const float* __restrict__ W1,
                                             const float* __restrict__ b1,
                                             const float* __restrict__ W2,
                                             const float* __restrict__ b2,
                                             float* __restrict__ hout) {
    constexpr int CINP = CIN + 4;  // pad to de-conflict z column reads
    extern __shared__ float sm[];
    float* W1s = sm;                  // CIN*64
    float* W2s = W1s + CIN * 64;      // 64*64
    float* b1s = W2s + 4096;          // 64
    float* b2s = b1s + 64;            // 64
    float* zsh = b2s + 64;            // 32*CINP
    float* tsh = zsh + 32 * CINP;     // 32*68

    int tid = threadIdx.x;
    for (int i = tid; i < CIN * 64; i += 256) W1s[i] = W1[i];
    for (int i = tid; i < 4096; i += 256) W2s[i] = W2[i];
    if (tid < 64) { b1s[tid] = b1[tid]; b2s[tid] = b2[tid]; }

    const int warp = tid >> 5, lane = tid & 31;
    const int ty = tid >> 4, tx = tid & 15;
    const int m0 = ty * 2, c0 = tx * 4;
    const int nTiles = (NN + 31) / 32;

    for (int tile = blockIdx.x; tile < nTiles; tile += gridDim.x) {
        __syncthreads();  // protect zsh/tsh from previous iteration's readers

        // ---- Phase A: aggregation (z = h + sum_{src in row(n)} h[src]) ----
        for (int s = 0; s < 4; s++) {
            int m = warp * 4 + s;
            int n = tile * 32 + m;
            if (n < NN) {
                int rs = g_rowptr[n];
                int re = g_rowptr[n + 1];
                if (CIN == 128) {
                    const float4* __restrict__ hin4 = (const float4*)hin;
                    float4 acc = hin4[n * 32 + lane];  // self term
                    for (int j0 = rs; j0 < re; j0 += 32) {
                        int myc = (j0 + lane < re) ? g_col[j0 + lane] : 0;
                        int cnt = min(32, re - j0);
                        int jj = 0;
                        for (; jj + 4 <= cnt; jj += 4) {
                            int s0 = __shfl_sync(0xffffffffu, myc, jj);
                            int s1 = __shfl_sync(0xffffffffu, myc, jj + 1);
                            int s2 = __shfl_sync(0xffffffffu, myc, jj + 2);
                            int s3 = __shfl_sync(0xffffffffu, myc, jj + 3);
                            float4 v0 = hin4[s0 * 32 + lane];
                            float4 v1 = hin4[s1 * 32 + lane];
                            float4 v2 = hin4[s2 * 32 + lane];
                            float4 v3 = hin4[s3 * 32 + lane];
                            acc.x += (v0.x + v1.x) + (v2.x + v3.x);
                            acc.y += (v0.y + v1.y) + (v2.y + v3.y);
                            acc.z += (v0.z + v1.z) + (v2.z + v3.z);
                            acc.w += (v0.w + v1.w) + (v2.w + v3.w);
                        }
                        for (; jj < cnt; jj++) {
                            int sj = __shfl_sync(0xffffffffu, myc, jj);
                            float4 v = hin4[sj * 32 + lane];
                            acc.x += v.x; acc.y += v.y; acc.z += v.z; acc.w += v.w;
                        }
                    }
                    *(float4*)&zsh[m * CINP + 4 * lane] = acc;
                } else {
                    const float2* __restrict__ hin2 = (const float2*)hin;
                    float2 acc = hin2[n * 32 + lane];
                    for (int j0 = rs; j0 < re; j0 += 32) {
                        int myc = (j0 + lane < re) ? g_col[j0 + lane] : 0;
                        int cnt = min(32, re - j0);
                        int jj = 0;
                        for (; jj + 4 <= cnt; jj += 4) {
                            int s0 = __shfl_sync(0xffffffffu, myc, jj);
                            int s1 = __shfl_sync(0xffffffffu, myc, jj + 1);
                            int s2 = __shfl_sync(0xffffffffu, myc, jj + 2);
                            int s3 = __shfl_sync(0xffffffffu, myc, jj + 3);
                            float2 v0 = hin2[s0 * 32 + lane];
                            float2 v1 = hin2[s1 * 32 + lane];
                            float2 v2 = hin2[s2 * 32 + lane];
                            float2 v3 = hin2[s3 * 32 + lane];
                            acc.x += (v0.x + v1.x) + (v2.x + v3.x);
                            acc.y += (v0.y + v1.y) + (v2.y + v3.y);
                        }
                        for (; jj < cnt; jj++) {
                            int sj = __shfl_sync(0xffffffffu, myc, jj);
                            float2 v = hin2[sj * 32 + lane];
                            acc.x += v.x; acc.y += v.y;
                        }
                    }
                    *(float2*)&zsh[m * CINP + 2 * lane] = acc;
                }
            } else {
                if (CIN == 128)
                    *(float4*)&zsh[m * CINP + 4 * lane] = make_float4(0.f, 0.f, 0.f, 0.f);
                else
                    *(float2*)&zsh[m * CINP + 2 * lane] = make_float2(0.f, 0.f);
            }
        }
        __syncthreads();

        // ---- Phase B1: t = relu(z @ W1 + b1), [32 x 64] ----
        {
            float4 a0 = *(const float4*)&b1s[c0];
            float4 a1 = a0;
#pragma unroll 8
            for (int k = 0; k < CIN; k++) {
                float4 w = *(const float4*)&W1s[k * 64 + c0];
                float z0 = zsh[(m0 + 0) * CINP + k];
                float z1 = zsh[(m0 + 1) * CINP + k];
                a0.x += z0 * w.x; a0.y += z0 * w.y; a0.z += z0 * w.z; a0.w += z0 * w.w;
                a1.x += z1 * w.x; a1.y += z1 * w.y; a1.z += z1 * w.z; a1.w += z1 * w.w;
            }
            a0.x = fmaxf(a0.x, 0.f); a0.y = fmaxf(a0.y, 0.f);
            a0.z = fmaxf(a0.z, 0.f); a0.w = fmaxf(a0.w, 0.f);
            a1.x = fmaxf(a1.x, 0.f); a1.y = fmaxf(a1.y, 0.f);
            a1.z = fmaxf(a1.z, 0.f); a1.w = fmaxf(a1.w, 0.f);
            *(float4*)&tsh[(m0 + 0) * 68 + c0] = a0;
            *(float4*)&tsh[(m0 + 1) * 68 + c0] = a1;
        }
        __syncthreads();

        // ---- Phase B2: h = relu(t @ W2 + b2) ----
        {
            float4 o0 = *(const float4*)&b2s[c0];
            float4 o1 = o0;
#pragma unroll 8
            for (int k = 0; k < 64; k++) {
                float4 w = *(const float4*)&W2s[k * 64 + c0];
                float t0 = tsh[(m0 + 0) * 68 + k];
                float t1 = tsh[(m0 + 1) * 68 + k];
                o0.x += t0 * w.x; o0.y += t0 * w.y; o0.z += t0 * w.z; o0.w += t0 * w.w;
                o1.x += t1 * w.x; o1.y += t1 * w.y; o1.z += t1 * w.z; o1.w += t1 * w.w;
            }
            o0.x = fmaxf(o0.x, 0.f); o0.y = fmaxf(o0.y, 0.f);
            o0.z = fmaxf(o0.z, 0.f); o0.w = fmaxf(o0.w, 0.f);
            o1.x = fmaxf(o1.x, 0.f); o1.y = fmaxf(o1.y, 0.f);
            o1.z = fmaxf(o1.z, 0.f); o1.w = fmaxf(o1.w, 0.f);
            int n0 = tile * 32 + m0;
            if (n0 < NN)     *(float4*)&hout[n0 * 64 + c0] = o0;
            if (n0 + 1 < NN) *(float4*)&hout[(n0 + 1) * 64 + c0] = o1;
        }
    }
}

// ---------------- per-layer global-add-pool into g_pool[:, loff:loff+64] ----------------
// batch is sorted: accumulate runs in registers, atomic-flush only at graph boundaries.
__global__ void k_pool(const float* __restrict__ h, const int* __restrict__ batch, int loff) {
    int c = threadIdx.x & 63;
    int s = threadIdx.x >> 6;
    int n0 = blockIdx.x * 256 + s * 64;
    float acc = 0.0f;
    int curg = -1;
    for (int i = 0; i < 64; i++) {
        int n = n0 + i;
        if (n >= NN) break;
        int g = batch[n];
        if (g != curg) {
            if (curg >= 0) atomicAdd(&g_pool[curg * 256 + loff + c], acc);
            acc = 0.0f;
            curg = g;
        }
        acc += h[n * 64 + c];
    }
    if (curg >= 0) atomicAdd(&g_pool[curg * 256 + loff + c], acc);
}

// ---------------- JK projection at graph granularity ----------------
// pooled[g] = g_pool[g,:] @ Wjk + cnt[g] * bjk   (pool/Wjk linearity swap)
__global__ void k_jk(const float* __restrict__ Wjk, const float* __restrict__ bjk) {
    int g = blockIdx.x;
    int c = threadIdx.x;  // 64
    float acc = (float)g_cnt[g] * bjk[c];
#pragma unroll 4
    for (int k = 0; k < 256; k++) acc += g_pool[g * 256 + k] * Wjk[k * 64 + c];
    g_pooledT[c * NG + g] = acc;  // transposed for coalesced reads in k_final
}

// ---------------- classifier: Linear -> BN(batch stats) -> ReLU -> Linear ----------------
__global__ __launch_bounds__(128) void k_final(const float* __restrict__ Wc1,
                                               const float* __restrict__ bc1,
                                               const float* __restrict__ gamma,
                                               const float* __restrict__ beta,
                                               const float* __restrict__ Wc2,
                                               const float* __restrict__ bc2,
                                               float* __restrict__ out) {
    extern __shared__ float sm[];
    float* Wc1s = sm;                  // 4096
    float* zsh = Wc1s + 4096;          // 128*66
    float* scv = zsh + 128 * 66;       // 64
    float* shv = scv + 64;             // 64
    int tid = threadIdx.x;  // = graph index g
    for (int i = tid; i < 4096; i += 128) Wc1s[i] = Wc1[i];
    __syncthreads();

    // z[g,:] = pooled[g,:] @ Wc1 + bc1
    float4 acc4[16];
#pragma unroll
    for (int c = 0; c < 16; c++) acc4[c] = *(const float4*)&bc1[c * 4];
    for (int k = 0; k < 64; k++) {
        float pk = g_pooledT[k * NG + tid];
#pragma unroll
        for (int c = 0; c < 16; c++) {
            float4 w = *(const float4*)&Wc1s[k * 64 + c * 4];
            acc4[c].x += pk * w.x; acc4[c].y += pk * w.y;
            acc4[c].z += pk * w.z; acc4[c].w += pk * w.w;
        }
    }
#pragma unroll
    for (int c = 0; c < 16; c++) {
        zsh[tid * 66 + c * 4 + 0] = acc4[c].x;
        zsh[tid * 66 + c * 4 + 1] = acc4[c].y;
        zsh[tid * 66 + c * 4 + 2] = acc4[c].z;
        zsh[tid * 66 + c * 4 + 3] = acc4[c].w;
    }
    __syncthreads();

    // batch-norm statistics over the 128 graphs, per channel
    if (tid < 64) {
        float s = 0.f, s2 = 0.f;
        for (int g = 0; g < 128; g++) {
            float v = zsh[g * 66 + tid];
            s += v;
            s2 += v * v;
        }
        float mu = s * (1.0f / 128.0f);
        float var = s2 * (1.0f / 128.0f) - mu * mu;
        float sc = gamma[tid] * rsqrtf(var + 1e-5f);
        scv[tid] = sc;
        shv[tid] = beta[tid] - mu * sc;
    }
    __syncthreads();

    // out[g,:] = relu(norm(z[g,:])) @ Wc2 + bc2
    float ao[10];
#pragma unroll
    for (int o = 0; o < 10; o++) ao[o] = bc2[o];
    for (int c = 0; c < 64; c++) {
        float v = fmaxf(zsh[tid * 66 + c] * scv[c] + shv[c], 0.0f);
#pragma unroll
        for (int o = 0; o < 10; o++) ao[o] += v * Wc2[c * 10 + o];
    }
#pragma unroll
    for (int o = 0; o < 10; o++) out[tid * 10 + o] = ao[o];
}

// ---------------- launch ----------------
extern "C" void kernel_launch(void* const* d_in, const int* in_sizes, int n_in,
                              void* d_out, int out_size) {
    const float* x    = (const float*)d_in[0];
    const int*   ei   = (const int*)d_in[1];
    const int*   batch= (const int*)d_in[2];
    const float* W1f  = (const float*)d_in[3];
    const float* b1f  = (const float*)d_in[4];
    const float* W2f  = (const float*)d_in[5];
    const float* b2f  = (const float*)d_in[6];
    const float* W1r  = (const float*)d_in[7];
    const float* b1r  = (const float*)d_in[8];
    const float* W2r  = (const float*)d_in[9];
    const float* b2r  = (const float*)d_in[10];
    const float* Wjk  = (const float*)d_in[11];
    const float* bjk  = (const float*)d_in[12];
    const float* Wc1  = (const float*)d_in[13];
    const float* bc1  = (const float*)d_in[14];
    const float* gamma= (const float*)d_in[15];
    const float* beta = (const float*)d_in[16];
    const float* Wc2  = (const float*)d_in[17];
    const float* bc2  = (const float*)d_in[18];
    float* out = (float*)d_out;

    float *h0p = 0, *h1p = 0;
    cudaGetSymbolAddress((void**)&h0p, g_h0);
    cudaGetSymbolAddress((void**)&h1p, g_h1);

    const size_t sm0 = (size_t)(128 * 64 + 4096 + 128 + 32 * (128 + 4) + 32 * 68) * sizeof(float);
    const size_t smh = (size_t)(64 * 64 + 4096 + 128 + 32 * (64 + 4) + 32 * 68) * sizeof(float);
    const size_t smf = (size_t)(4096 + 128 * 66 + 128) * sizeof(float);
    cudaFuncSetAttribute(k_gin<128>, cudaFuncAttributeMaxDynamicSharedMemorySize, (int)sm0);
    cudaFuncSetAttribute(k_gin<64>,  cudaFuncAttributeMaxDynamicSharedMemorySize, (int)smh);
    cudaFuncSetAttribute(k_final,    cudaFuncAttributeMaxDynamicSharedMemorySize, (int)smf);

    // CSR build (reused by all 4 layers) + zeroed accumulators
    k_zero<<<256, 256>>>();
    k_hist<<<(NE + 255) / 256, 256>>>(ei);
    k_cnt<<<(NN + 255) / 256, 256>>>(batch);
    k_scan1<<<NB, 1024>>>();
    k_scan2<<<1, 128>>>();
    k_scan3<<<NB, 1024>>>();
    k_fill<<<(NE + 255) / 256, 256>>>(ei);

    const int POOL_GRID = (NN + 255) / 256;
    // layer 0 (128 -> 64)
    k_gin<128><<<444, 256, sm0>>>(x, W1f, b1f, W2f, b2f, h0p);
    k_pool<<<POOL_GRID, 256>>>(h0p, batch, 0);
    // layers 1..3 (64 -> 64), ping-pong h0/h1
    k_gin<64><<<592, 256, smh>>>(h0p, W1r, b1r, W2r, b2r, h1p);
    k_pool<<<POOL_GRID, 256>>>(h1p, batch, 64);
    k_gin<64><<<592, 256, smh>>>(h1p, W1r + 4096, b1r + 64, W2r + 4096, b2r + 64, h0p);
    k_pool<<<POOL_GRID, 256>>>(h0p, batch, 128);
    k_gin<64><<<592, 256, smh>>>(h0p, W1r + 2 * 4096, b1r + 2 * 64, W2r + 2 * 4096, b2r + 2 * 64, h1p);
    k_pool<<<POOL_GRID, 256>>>(h1p, batch, 192);

    // JK cat @ Wjk at graph granularity, then classifier + BN
    k_jk<<<NG, 64>>>(Wjk, bjk);
    k_final<<<1, 128, smf>>>(Wc1, bc1, gamma, beta, Wc2, bc2, out);
}

// round 3
// speedup vs baseline: 1.3061x; 1.0705x over previous
#include <cuda_runtime.h>

#define NN 100000
#define NE 1600000
#define NG 128
#define HID 64
#define NB 98   // ceil(NN / 1024)

// ---------------- scratch (device globals: allocation-free) ----------------
// NOTE: accumulated-into buffers (g_deg, g_pool, g_cnt, g_lb) are zeroed at the
// END of each kernel_launch (k_zero_post). Module-load zero-init covers call 1.
__device__ int   g_deg[NN];
__device__ int   g_rowptr[NN + 1];
__device__ int   g_cursor[NN];
__device__ int   g_col[NE];
__device__ unsigned long long g_lb[NB];  // lookback scan state (flag<<62 | value)
__device__ float g_h0[NN * HID];
__device__ float g_h1[NN * HID];
__device__ float g_pool[NG * 4 * HID];   // pooled per-layer h, [G][256]
__device__ int   g_cnt[NG];
__device__ float g_pooledT[HID * NG];    // JK output, transposed [c][g]

// ---------------- CSR build: histogram over dst ----------------
__global__ void k_hist(const int* __restrict__ ei) {
    int e = blockIdx.x * blockDim.x + threadIdx.x;
    if (e < NE) atomicAdd(&g_deg[ei[NE + e]], 1);
}

// single-pass decoupled-lookback exclusive scan: g_deg -> g_rowptr/g_cursor
// 98 blocks <= 148 SMs -> whole grid resident in wave 1 (no deadlock).
__global__ __launch_bounds__(1024) void k_scanlb() {
    __shared__ int s[1024];
    __shared__ int s_base;
    int t = threadIdx.x, b = blockIdx.x;
    int i = b * 1024 + t;
    int v = (i < NN) ? g_deg[i] : 0;
    s[t] = v;
    __syncthreads();
#pragma unroll
    for (int off = 1; off < 1024; off <<= 1) {
        int u = (t >= off) ? s[t - off] : 0;
        __syncthreads();
        s[t] += u;
        __syncthreads();
    }
    int agg = s[1023];
    if (t == 0) {
        if (b == 0) {
            atomicExch(&g_lb[0], (2ULL << 62) | (unsigned)agg);
            s_base = 0;
        } else {
            atomicExch(&g_lb[b], (1ULL << 62) | (unsigned)agg);
            int running = 0;
            int j = b - 1;
            while (true) {
                unsigned long long x;
                do { x = atomicAdd(&g_lb[j], 0ULL); } while ((x >> 62) == 0);
                running += (int)(unsigned)(x & 0xffffffffULL);
                if ((x >> 62) == 2ULL) break;
                j--;
            }
            atomicExch(&g_lb[b], (2ULL << 62) | (unsigned)(running + agg));
            s_base = running;
        }
    }
    __syncthreads();
    if (i < NN) {
        int ex = s[t] - v + s_base;
        g_rowptr[i] = ex;
        g_cursor[i] = ex;
    }
    if (i == 0) g_rowptr[NN] = NE;  // every edge lands in exactly one dst bucket
}

// fill CSR col (src indices) keyed by dst
__global__ void k_fill(const int* __restrict__ ei) {
    int e = blockIdx.x * blockDim.x + threadIdx.x;
    if (e < NE) {
        int d = ei[NE + e];
        int slot = atomicAdd(&g_cursor[d], 1);
        g_col[slot] = ei[e];
    }
}

// nodes-per-graph histogram (warp-aggregated; batch is sorted)
__global__ void k_cnt(const int* __restrict__ batch) {
    int n = blockIdx.x * blockDim.x + threadIdx.x;
    unsigned am = __ballot_sync(0xffffffffu, n < NN);
    if (n < NN) {
        int g = batch[n];
        unsigned mask = __match_any_sync(am, g);
        int leader = __ffs(mask) - 1;
        if ((threadIdx.x & 31) == leader) atomicAdd(&g_cnt[g], __popc(mask));
    }
}

// ---------------- fused GIN layer: aggregate + MLP(2 stage) + relu ----------------
// block = 256 threads, node tile of 32 (NN % 32 == 0, no bounds checks).
template <int CIN>
__global__ __launch_bounds__(256) void k_gin(const float* __restrict__ hin,
                                             const float* __restrict__ W1,
                                             const float* __restrict__ b1,
                                             const float* __restrict__ W2,
                                             const float* __restrict__ b2,
                                             float* __restrict__ hout) {
    constexpr int CINP = CIN + 4;  // pad to de-conflict z column reads
    extern __shared__ float sm[];
    float* W1s = sm;                  // CIN*64
    float* W2s = W1s + CIN * 64;      // 64*64
    float* b1s = W2s + 4096;          // 64
    float* b2s = b1s + 64;            // 64
    float* zsh = b2s + 64;            // 32*CINP
    float* tsh = zsh + 32 * CINP;     // 32*68

    int tid = threadIdx.x;
    for (int i = tid; i < CIN * 64; i += 256) W1s[i] = W1[i];
    for (int i = tid; i < 4096; i += 256) W2s[i] = W2[i];
    if (tid < 64) { b1s[tid] = b1[tid]; b2s[tid] = b2[tid]; }

    const int warp = tid >> 5, lane = tid & 31;
    const int ty = tid >> 4, tx = tid & 15;
    const int m0 = ty * 2, c0 = tx * 4;
    const int nTiles = NN / 32;
    const float4* __restrict__ hin4 = (const float4*)hin;

    for (int tile = blockIdx.x; tile < nTiles; tile += gridDim.x) {
        __syncthreads();  // protect zsh/tsh from previous iteration's readers

        // ---- Phase A: aggregation (z = h + sum_{src in row(n)} h[src]) ----
        if (CIN == 128) {
            // full-warp rows: 32 lanes x float4 = 128 floats
            for (int s = 0; s < 4; s++) {
                int m = warp * 4 + s;
                int n = tile * 32 + m;
                float4 acc = hin4[n * 32 + lane];  // self term
                int rs = g_rowptr[n];
                int re = g_rowptr[n + 1];
                for (int j0 = rs; j0 < re; j0 += 32) {
                    int myc = (j0 + lane < re) ? g_col[j0 + lane] : 0;
                    int cnt = min(32, re - j0);
                    int jj = 0;
                    for (; jj + 8 <= cnt; jj += 8) {
                        int s0 = __shfl_sync(0xffffffffu, myc, jj);
                        int s1 = __shfl_sync(0xffffffffu, myc, jj + 1);
                        int s2 = __shfl_sync(0xffffffffu, myc, jj + 2);
                        int s3 = __shfl_sync(0xffffffffu, myc, jj + 3);
                        int s4 = __shfl_sync(0xffffffffu, myc, jj + 4);
                        int s5 = __shfl_sync(0xffffffffu, myc, jj + 5);
                        int s6 = __shfl_sync(0xffffffffu, myc, jj + 6);
                        int s7 = __shfl_sync(0xffffffffu, myc, jj + 7);
                        float4 v0 = hin4[s0 * 32 + lane];
                        float4 v1 = hin4[s1 * 32 + lane];
                        float4 v2 = hin4[s2 * 32 + lane];
                        float4 v3 = hin4[s3 * 32 + lane];
                        float4 v4 = hin4[s4 * 32 + lane];
                        float4 v5 = hin4[s5 * 32 + lane];
                        float4 v6 = hin4[s6 * 32 + lane];
                        float4 v7 = hin4[s7 * 32 + lane];
                        acc.x += ((v0.x + v1.x) + (v2.x + v3.x)) + ((v4.x + v5.x) + (v6.x + v7.x));
                        acc.y += ((v0.y + v1.y) + (v2.y + v3.y)) + ((v4.y + v5.y) + (v6.y + v7.y));
                        acc.z += ((v0.z + v1.z) + (v2.z + v3.z)) + ((v4.z + v5.z) + (v6.z + v7.z));
                        acc.w += ((v0.w + v1.w) + (v2.w + v3.w)) + ((v4.w + v5.w) + (v6.w + v7.w));
                    }
                    for (; jj < cnt; jj++) {
                        int sj = __shfl_sync(0xffffffffu, myc, jj);
                        float4 v = hin4[sj * 32 + lane];
                        acc.x += v.x; acc.y += v.y; acc.z += v.z; acc.w += v.w;
                    }
                }
                *(float4*)&zsh[m * CINP + 4 * lane] = acc;
            }
        } else {
            // half-warp rows: 16 lanes x float4 = 64 floats; 2 edges per LDG inst
            const int half = lane >> 4;
            const int l16 = lane & 15;
            const unsigned hm = 0xFFFFu << (half * 16);
            for (int s = 0; s < 2; s++) {
                int m = warp * 4 + s * 2 + half;
                int n = tile * 32 + m;
                float4 acc = hin4[n * 16 + l16];  // self term
                int rs = g_rowptr[n];
                int re = g_rowptr[n + 1];
                for (int j0 = rs; j0 < re; j0 += 16) {
                    int myc = (j0 + l16 < re) ? g_col[j0 + l16] : 0;
                    int cnt = min(16, re - j0);
                    int jj = 0;
                    for (; jj + 4 <= cnt; jj += 4) {
                        int s0 = __shfl_sync(hm, myc, jj, 16);
                        int s1 = __shfl_sync(hm, myc, jj + 1, 16);
                        int s2 = __shfl_sync(hm, myc, jj + 2, 16);
                        int s3 = __shfl_sync(hm, myc, jj + 3, 16);
                        float4 v0 = hin4[s0 * 16 + l16];
                        float4 v1 = hin4[s1 * 16 + l16];
                        float4 v2 = hin4[s2 * 16 + l16];
                        float4 v3 = hin4[s3 * 16 + l16];
                        acc.x += (v0.x + v1.x) + (v2.x + v3.x);
                        acc.y += (v0.y + v1.y) + (v2.y + v3.y);
                        acc.z += (v0.z + v1.z) + (v2.z + v3.z);
                        acc.w += (v0.w + v1.w) + (v2.w + v3.w);
                    }
                    for (; jj < cnt; jj++) {
                        int sj = __shfl_sync(hm, myc, jj, 16);
                        float4 v = hin4[sj * 16 + l16];
                        acc.x += v.x; acc.y += v.y; acc.z += v.z; acc.w += v.w;
                    }
                }
                *(float4*)&zsh[m * CINP + 4 * l16] = acc;
            }
        }
        __syncthreads();

        // ---- Phase B1: t = relu(z @ W1 + b1), [32 x 64] ----
        {
            float4 a0 = *(const float4*)&b1s[c0];
            float4 a1 = a0;
#pragma unroll 8
            for (int k = 0; k < CIN; k++) {
                float4 w = *(const float4*)&W1s[k * 64 + c0];
                float z0 = zsh[(m0 + 0) * CINP + k];
                float z1 = zsh[(m0 + 1) * CINP + k];
                a0.x += z0 * w.x; a0.y += z0 * w.y; a0.z += z0 * w.z; a0.w += z0 * w.w;
                a1.x += z1 * w.x; a1.y += z1 * w.y; a1.z += z1 * w.z; a1.w += z1 * w.w;
            }
            a0.x = fmaxf(a0.x, 0.f); a0.y = fmaxf(a0.y, 0.f);
            a0.z = fmaxf(a0.z, 0.f); a0.w = fmaxf(a0.w, 0.f);
            a1.x = fmaxf(a1.x, 0.f); a1.y = fmaxf(a1.y, 0.f);
            a1.z = fmaxf(a1.z, 0.f); a1.w = fmaxf(a1.w, 0.f);
            *(float4*)&tsh[(m0 + 0) * 68 + c0] = a0;
            *(float4*)&tsh[(m0 + 1) * 68 + c0] = a1;
        }
        __syncthreads();

        // ---- Phase B2: h = relu(t @ W2 + b2) ----
        {
            float4 o0 = *(const float4*)&b2s[c0];
            float4 o1 = o0;
#pragma unroll 8
            for (int k = 0; k < 64; k++) {
                float4 w = *(const float4*)&W2s[k * 64 + c0];
                float t0 = tsh[(m0 + 0) * 68 + k];
                float t1 = tsh[(m0 + 1) * 68 + k];
                o0.x += t0 * w.x; o0.y += t0 * w.y; o0.z += t0 * w.z; o0.w += t0 * w.w;
                o1.x += t1 * w.x; o1.y += t1 * w.y; o1.z += t1 * w.z; o1.w += t1 * w.w;
            }
            o0.x = fmaxf(o0.x, 0.f); o0.y = fmaxf(o0.y, 0.f);
            o0.z = fmaxf(o0.z, 0.f); o0.w = fmaxf(o0.w, 0.f);
            o1.x = fmaxf(o1.x, 0.f); o1.y = fmaxf(o1.y, 0.f);
            o1.z = fmaxf(o1.z, 0.f); o1.w = fmaxf(o1.w, 0.f);
            int n0 = tile * 32 + m0;
            *(float4*)&hout[n0 * 64 + c0] = o0;
            *(float4*)&hout[(n0 + 1) * 64 + c0] = o1;
        }
    }
}

// ---------------- per-layer global-add-pool into g_pool[:, loff:loff+64] ----------------
// batch is sorted: accumulate runs in registers, atomic-flush only at graph boundaries.
__global__ void k_pool(const float* __restrict__ h, const int* __restrict__ batch, int loff) {
    int c = threadIdx.x & 63;
    int s = threadIdx.x >> 6;
    int n0 = blockIdx.x * 256 + s * 64;
    float acc = 0.0f;
    int curg = -1;
    for (int i = 0; i < 64; i++) {
        int n = n0 + i;
        if (n >= NN) break;
        int g = batch[n];
        if (g != curg) {
            if (curg >= 0) atomicAdd(&g_pool[curg * 256 + loff + c], acc);
            acc = 0.0f;
            curg = g;
        }
        acc += h[n * 64 + c];
    }
    if (curg >= 0) atomicAdd(&g_pool[curg * 256 + loff + c], acc);
}

// ---------------- JK projection at graph granularity ----------------
// pooled[g] = g_pool[g,:] @ Wjk + cnt[g] * bjk   (pool/Wjk linearity swap)
__global__ void k_jk(const float* __restrict__ Wjk, const float* __restrict__ bjk) {
    int g = blockIdx.x;
    int c = threadIdx.x;  // 64
    float acc = (float)g_cnt[g] * bjk[c];
#pragma unroll 4
    for (int k = 0; k < 256; k++) acc += g_pool[g * 256 + k] * Wjk[k * 64 + c];
    g_pooledT[c * NG + g] = acc;  // transposed for coalesced reads in k_final
}

// ---------------- classifier: Linear -> BN(batch stats) -> ReLU -> Linear ----------------
__global__ __launch_bounds__(128) void k_final(const float* __restrict__ Wc1,
                                               const float* __restrict__ bc1,
                                               const float* __restrict__ gamma,
                                               const float* __restrict__ beta,
                                               const float* __restrict__ Wc2,
                                               const float* __restrict__ bc2,
                                               float* __restrict__ out) {
    extern __shared__ float sm[];
    float* Wc1s = sm;                  // 4096
    float* zsh = Wc1s + 4096;          // 128*66
    float* scv = zsh + 128 * 66;       // 64
    float* shv = scv + 64;             // 64
    int tid = threadIdx.x;  // = graph index g
    for (int i = tid; i < 4096; i += 128) Wc1s[i] = Wc1[i];
    __syncthreads();

    // z[g,:] = pooled[g,:] @ Wc1 + bc1
    float4 acc4[16];
#pragma unroll
    for (int c = 0; c < 16; c++) acc4[c] = *(const float4*)&bc1[c * 4];
    for (int k = 0; k < 64; k++) {
        float pk = g_pooledT[k * NG + tid];
#pragma unroll
        for (int c = 0; c < 16; c++) {
            float4 w = *(const float4*)&Wc1s[k * 64 + c * 4];
            acc4[c].x += pk * w.x; acc4[c].y += pk * w.y;
            acc4[c].z += pk * w.z; acc4[c].w += pk * w.w;
        }
    }
#pragma unroll
    for (int c = 0; c < 16; c++) {
        zsh[tid * 66 + c * 4 + 0] = acc4[c].x;
        zsh[tid * 66 + c * 4 + 1] = acc4[c].y;
        zsh[tid * 66 + c * 4 + 2] = acc4[c].z;
        zsh[tid * 66 + c * 4 + 3] = acc4[c].w;
    }
    __syncthreads();

    // batch-norm statistics over the 128 graphs, per channel
    if (tid < 64) {
        float s = 0.f, s2 = 0.f;
        for (int g = 0; g < 128; g++) {
            float v = zsh[g * 66 + tid];
            s += v;
            s2 += v * v;
        }
        float mu = s * (1.0f / 128.0f);
        float var = s2 * (1.0f / 128.0f) - mu * mu;
        float sc = gamma[tid] * rsqrtf(var + 1e-5f);
        scv[tid] = sc;
        shv[tid] = beta[tid] - mu * sc;
    }
    __syncthreads();

    // out[g,:] = relu(norm(z[g,:])) @ Wc2 + bc2
    float ao[10];
#pragma unroll
    for (int o = 0; o < 10; o++) ao[o] = bc2[o];
    for (int c = 0; c < 64; c++) {
        float v = fmaxf(zsh[tid * 66 + c] * scv[c] + shv[c], 0.0f);
#pragma unroll
        for (int o = 0; o < 10; o++) ao[o] += v * Wc2[c * 10 + o];
    }
#pragma unroll
    for (int o = 0; o < 10; o++) out[tid * 10 + o] = ao[o];
}

// ---------------- end-of-call zeroing (prepares NEXT call; module init covers call 1) ----
__global__ void k_zero_post() {
    int i = blockIdx.x * blockDim.x + threadIdx.x;
    int stride = gridDim.x * blockDim.x;
    for (int j = i; j < NN; j += stride) g_deg[j] = 0;
    for (int j = i; j < NG * 4 * HID; j += stride) g_pool[j] = 0.0f;
    for (int j = i; j < NG; j += stride) g_cnt[j] = 0;
    for (int j = i; j < NB; j += stride) g_lb[j] = 0ULL;
}

// ---------------- launch ----------------
extern "C" void kernel_launch(void* const* d_in, const int* in_sizes, int n_in,
                              void* d_out, int out_size) {
    const float* x    = (const float*)d_in[0];
    const int*   ei   = (const int*)d_in[1];
    const int*   batch= (const int*)d_in[2];
    const float* W1f  = (const float*)d_in[3];
    const float* b1f  = (const float*)d_in[4];
    const float* W2f  = (const float*)d_in[5];
    const float* b2f  = (const float*)d_in[6];
    const float* W1r  = (const float*)d_in[7];
    const float* b1r  = (const float*)d_in[8];
    const float* W2r  = (const float*)d_in[9];
    const float* b2r  = (const float*)d_in[10];
    const float* Wjk  = (const float*)d_in[11];
    const float* bjk  = (const float*)d_in[12];
    const float* Wc1  = (const float*)d_in[13];
    const float* bc1  = (const float*)d_in[14];
    const float* gamma= (const float*)d_in[15];
    const float* beta = (const float*)d_in[16];
    const float* Wc2  = (const float*)d_in[17];
    const float* bc2  = (const float*)d_in[18];
    float* out = (float*)d_out;

    float *h0p = 0, *h1p = 0;
    cudaGetSymbolAddress((void**)&h0p, g_h0);
    cudaGetSymbolAddress((void**)&h1p, g_h1);

    const size_t sm0 = (size_t)(128 * 64 + 4096 + 128 + 32 * (128 + 4) + 32 * 68) * sizeof(float);
    const size_t smh = (size_t)(64 * 64 + 4096 + 128 + 32 * (64 + 4) + 32 * 68) * sizeof(float);
    const size_t smf = (size_t)(4096 + 128 * 66 + 128) * sizeof(float);
    cudaFuncSetAttribute(k_gin<128>, cudaFuncAttributeMaxDynamicSharedMemorySize, (int)sm0);
    cudaFuncSetAttribute(k_gin<64>,  cudaFuncAttributeMaxDynamicSharedMemorySize, (int)smh);
    cudaFuncSetAttribute(k_final,    cudaFuncAttributeMaxDynamicSharedMemorySize, (int)smf);

    // CSR build (scratch pre-zeroed by previous call's k_zero_post / module init)
    k_hist<<<(NE + 255) / 256, 256>>>(ei);      // launch 1
    k_scanlb<<<NB, 1024>>>();                   // launch 2
    k_fill<<<(NE + 255) / 256, 256>>>(ei);      // launch 3

    const int POOL_GRID = (NN + 255) / 256;
    // layer 0 (128 -> 64)  — launch 4: profiled slot
    k_gin<128><<<444, 256, sm0>>>(x, W1f, b1f, W2f, b2f, h0p);
    k_pool<<<POOL_GRID, 256>>>(h0p, batch, 0);
    // layers 1..3 (64 -> 64), ping-pong h0/h1
    k_gin<64><<<592, 256, smh>>>(h0p, W1r, b1r, W2r, b2r, h1p);
    k_pool<<<POOL_GRID, 256>>>(h1p, batch, 64);
    k_gin<64><<<592, 256, smh>>>(h1p, W1r + 4096, b1r + 64, W2r + 4096, b2r + 64, h0p);
    k_pool<<<POOL_GRID, 256>>>(h0p, batch, 128);
    k_gin<64><<<592, 256, smh>>>(h0p, W1r + 2 * 4096, b1r + 2 * 64, W2r + 2 * 4096, b2r + 2 * 64, h1p);
    k_pool<<<POOL_GRID, 256>>>(h1p, batch, 192);

    // graph-granularity tail
    k_cnt<<<(NN + 255) / 256, 256>>>(batch);
    k_jk<<<NG, 64>>>(Wjk, bjk);
    k_final<<<1, 128, smf>>>(Wc1, bc1, gamma, beta, Wc2, bc2, out);

    // zero accumulators for the NEXT call (after all readers above)
    k_zero_post<<<256, 256>>>();
}

// round 4
// speedup vs baseline: 1.5062x; 1.1532x over previous
#include <cuda_runtime.h>

#define NN 100000
#define NE 1600000
#define NG 128
#define HID 64
#define NB 98       // ceil(NN / 1024)
#define NTILES 3125 // NN / 32

// ---------------- scratch (device globals: allocation-free) ----------------
// accumulated-into buffers (g_deg, g_pool, g_cnt, g_lb) are zeroed at the END
// of each kernel_launch (k_zero_post). Module-load zero-init covers call 1.
__device__ int   g_deg[NN];
__device__ int   g_rowptr[NN + 1];
__device__ int   g_cursor[NN];
__device__ int   g_col[NE];
__device__ unsigned long long g_lb[NB];  // lookback scan state (flag<<62 | value)
__device__ float g_h0[NN * HID];
__device__ float g_h1[NN * HID];
__device__ float g_pool[NG * 4 * HID];   // pooled per-layer h', [G][256]
__device__ int   g_cnt[NG];
__device__ float g_pooledT[HID * NG];    // JK output, transposed [c][g]

// ---------------- launch 0: fused y0 = x @ W1f  +  deg histogram  +  graph counts ----
__global__ __launch_bounds__(256) void k_pre_hist(const float* __restrict__ x,
                                                  const float* __restrict__ W1f,
                                                  const int* __restrict__ ei,
                                                  const int* __restrict__ batch,
                                                  float* __restrict__ y0) {
    extern __shared__ float sm[];
    float* W1s = sm;          // 128*64 = 8192
    float* xs  = sm + 8192;   // 32*132
    int tid = threadIdx.x;
    for (int i = tid; i < 8192; i += 256) W1s[i] = W1f[i];
    const int ty = tid >> 4, tx = tid & 15;
    const int m0 = ty * 2, c0 = tx * 4;
    const float4* __restrict__ x4 = (const float4*)x;

    for (int tile = blockIdx.x; tile < NTILES; tile += gridDim.x) {
        __syncthreads();
        // --- degree histogram: 512 edges per tile (3125*512 = NE exactly) ---
        {
            int e0 = tile * 512;
            int d0 = ei[NE + e0 + tid];
            int d1 = ei[NE + e0 + 256 + tid];
            atomicAdd(&g_deg[d0], 1);
            atomicAdd(&g_deg[d1], 1);
        }
        // --- nodes-per-graph counts (warp 0, batch sorted) ---
        if (tid < 32) {
            int g = batch[tile * 32 + tid];
            unsigned mask = __match_any_sync(0xffffffffu, g);
            if (tid == __ffs(mask) - 1) atomicAdd(&g_cnt[g], __popc(mask));
        }
        // --- load x tile [32 x 128] coalesced ---
#pragma unroll
        for (int i = 0; i < 4; i++) {
            int j = tid + i * 256;       // 0..1023
            int r = j >> 5, cv = j & 31;
            *(float4*)&xs[r * 132 + cv * 4] = x4[(tile * 32 + r) * 32 + cv];
        }
        __syncthreads();
        // --- y = x @ W1f (no bias, no relu: bias folded into layer kernel) ---
        float4 a0 = make_float4(0.f, 0.f, 0.f, 0.f), a1 = a0;
#pragma unroll 8
        for (int k = 0; k < 128; k++) {
            float4 w = *(const float4*)&W1s[k * 64 + c0];
            float z0 = xs[(m0 + 0) * 132 + k];
            float z1 = xs[(m0 + 1) * 132 + k];
            a0.x += z0 * w.x; a0.y += z0 * w.y; a0.z += z0 * w.z; a0.w += z0 * w.w;
            a1.x += z1 * w.x; a1.y += z1 * w.y; a1.z += z1 * w.z; a1.w += z1 * w.w;
        }
        int n0 = tile * 32 + m0;
        *(float4*)&y0[n0 * 64 + c0] = a0;
        *(float4*)&y0[(n0 + 1) * 64 + c0] = a1;
    }
}

// ---------------- single-pass decoupled-lookback exclusive scan ----------------
__global__ __launch_bounds__(1024) void k_scanlb() {
    __shared__ int s[1024];
    __shared__ int s_base;
    int t = threadIdx.x, b = blockIdx.x;
    int i = b * 1024 + t;
    int v = (i < NN) ? g_deg[i] : 0;
    s[t] = v;
    __syncthreads();
#pragma unroll
    for (int off = 1; off < 1024; off <<= 1) {
        int u = (t >= off) ? s[t - off] : 0;
        __syncthreads();
        s[t] += u;
        __syncthreads();
    }
    int agg = s[1023];
    if (t == 0) {
        if (b == 0) {
            atomicExch(&g_lb[0], (2ULL << 62) | (unsigned)agg);
            s_base = 0;
        } else {
            atomicExch(&g_lb[b], (1ULL << 62) | (unsigned)agg);
            int running = 0;
            int j = b - 1;
            while (true) {
                unsigned long long xx;
                do { xx = atomicAdd(&g_lb[j], 0ULL); } while ((xx >> 62) == 0);
                running += (int)(unsigned)(xx & 0xffffffffULL);
                if ((xx >> 62) == 2ULL) break;
                j--;
            }
            atomicExch(&g_lb[b], (2ULL << 62) | (unsigned)(running + agg));
            s_base = running;
        }
    }
    __syncthreads();
    if (i < NN) {
        int ex = s[t] - v + s_base;
        g_rowptr[i] = ex;
        g_cursor[i] = ex;
    }
    if (i == 0) g_rowptr[NN] = NE;
}

// fill CSR col (src indices) keyed by dst
__global__ void k_fill(const int* __restrict__ ei) {
    int e = blockIdx.x * blockDim.x + threadIdx.x;
    if (e < NE) {
        int d = ei[NE + e];
        int slot = atomicAdd(&g_cursor[d], 1);
        g_col[slot] = ei[e];
    }
}

// ---------------- fused GIN layer on pre-transformed features ----------------
// input y = h @ W1 per node (64-dim). Computes:
//   t  = relu(y_self + agg(y) + b1)      (gather in 64-dim)
//   h' = relu(t @ W2 + b2)
//   pool: g_pool[batch[n], loff + c] += h'[n][c]   (in-kernel, run-accumulated)
//   y_next = h' @ W1next                 (skipped when LAST)
template <bool LAST>
__global__ __launch_bounds__(256) void k_layer(const float* __restrict__ yin,
                                               const float* __restrict__ b1,
                                               const float* __restrict__ W2,
                                               const float* __restrict__ b2,
                                               const float* __restrict__ W1n,
                                               const int* __restrict__ batch,
                                               float* __restrict__ ynext,
                                               int loff) {
    constexpr int W1N_SZ = LAST ? 0 : 4096;
    extern __shared__ float sm[];
    float* W2s  = sm;                        // 4096
    float* W1ns = sm + 4096;                 // 4096 (absent when LAST)
    float* b1s  = sm + 4096 + W1N_SZ;        // 64
    float* b2s  = b1s + 64;                  // 64
    float* zsh  = b2s + 64;                  // 32*68  (holds t)
    float* tsh  = zsh + 32 * 68;             // 32*68  (holds h')
    __shared__ int sbatch[32];

    int tid = threadIdx.x;
    for (int i = tid; i < 4096; i += 256) W2s[i] = W2[i];
    if (!LAST) for (int i = tid; i < 4096; i += 256) W1ns[i] = W1n[i];
    if (tid < 64) { b1s[tid] = b1[tid]; b2s[tid] = b2[tid]; }

    const int warp = tid >> 5, lane = tid & 31;
    const int half = lane >> 4, l16 = lane & 15;
    const unsigned hm = 0xFFFFu << (half * 16);
    const int ty = tid >> 4, tx = tid & 15;
    const int m0 = ty * 2, c0 = tx * 4;
    const float4* __restrict__ yin4 = (const float4*)yin;

    for (int tile = blockIdx.x; tile < NTILES; tile += gridDim.x) {
        __syncthreads();  // protect zsh/tsh/sbatch from previous iteration's readers
        if (tid < 32) sbatch[tid] = batch[tile * 32 + tid];

        // ---- gather: t = relu(y_self + agg(y) + b1), half-warp rows ----
        {
            float4 bb = *(const float4*)&b1s[4 * l16];
            for (int s = 0; s < 2; s++) {
                int m = warp * 4 + s * 2 + half;
                int n = tile * 32 + m;
                float4 acc = yin4[n * 16 + l16];  // self term
                int rs = g_rowptr[n];
                int re = g_rowptr[n + 1];
                for (int j0 = rs; j0 < re; j0 += 16) {
                    int myc = (j0 + l16 < re) ? g_col[j0 + l16] : 0;
                    int cnt = min(16, re - j0);
                    int jj = 0;
                    for (; jj + 4 <= cnt; jj += 4) {
                        int s0 = __shfl_sync(hm, myc, jj, 16);
                        int s1 = __shfl_sync(hm, myc, jj + 1, 16);
                        int s2 = __shfl_sync(hm, myc, jj + 2, 16);
                        int s3 = __shfl_sync(hm, myc, jj + 3, 16);
                        float4 v0 = yin4[s0 * 16 + l16];
                        float4 v1 = yin4[s1 * 16 + l16];
                        float4 v2 = yin4[s2 * 16 + l16];
                        float4 v3 = yin4[s3 * 16 + l16];
                        acc.x += (v0.x + v1.x) + (v2.x + v3.x);
                        acc.y += (v0.y + v1.y) + (v2.y + v3.y);
                        acc.z += (v0.z + v1.z) + (v2.z + v3.z);
                        acc.w += (v0.w + v1.w) + (v2.w + v3.w);
                    }
                    for (; jj < cnt; jj++) {
                        int sj = __shfl_sync(hm, myc, jj, 16);
                        float4 v = yin4[sj * 16 + l16];
                        acc.x += v.x; acc.y += v.y; acc.z += v.z; acc.w += v.w;
                    }
                }
                acc.x = fmaxf(acc.x + bb.x, 0.f);
                acc.y = fmaxf(acc.y + bb.y, 0.f);
                acc.z = fmaxf(acc.z + bb.z, 0.f);
                acc.w = fmaxf(acc.w + bb.w, 0.f);
                *(float4*)&zsh[m * 68 + 4 * l16] = acc;
            }
        }
        __syncthreads();

        // ---- h' = relu(t @ W2 + b2) -> tsh ----
        {
            float4 o0 = *(const float4*)&b2s[c0];
            float4 o1 = o0;
#pragma unroll 8
            for (int k = 0; k < 64; k++) {
                float4 w = *(const float4*)&W2s[k * 64 + c0];
                float t0 = zsh[(m0 + 0) * 68 + k];
                float t1 = zsh[(m0 + 1) * 68 + k];
                o0.x += t0 * w.x; o0.y += t0 * w.y; o0.z += t0 * w.z; o0.w += t0 * w.w;
                o1.x += t1 * w.x; o1.y += t1 * w.y; o1.z += t1 * w.z; o1.w += t1 * w.w;
            }
            o0.x = fmaxf(o0.x, 0.f); o0.y = fmaxf(o0.y, 0.f);
            o0.z = fmaxf(o0.z, 0.f); o0.w = fmaxf(o0.w, 0.f);
            o1.x = fmaxf(o1.x, 0.f); o1.y = fmaxf(o1.y, 0.f);
            o1.z = fmaxf(o1.z, 0.f); o1.w = fmaxf(o1.w, 0.f);
            *(float4*)&tsh[(m0 + 0) * 68 + c0] = o0;
            *(float4*)&tsh[(m0 + 1) * 68 + c0] = o1;
        }
        __syncthreads();

        // ---- y_next = h' @ W1next -> global (skipped on last layer) ----
        if (!LAST) {
            float4 o0 = make_float4(0.f, 0.f, 0.f, 0.f), o1 = o0;
#pragma unroll 8
            for (int k = 0; k < 64; k++) {
                float4 w = *(const float4*)&W1ns[k * 64 + c0];
                float t0 = tsh[(m0 + 0) * 68 + k];
                float t1 = tsh[(m0 + 1) * 68 + k];
                o0.x += t0 * w.x; o0.y += t0 * w.y; o0.z += t0 * w.z; o0.w += t0 * w.w;
                o1.x += t1 * w.x; o1.y += t1 * w.y; o1.z += t1 * w.z; o1.w += t1 * w.w;
            }
            int n0 = tile * 32 + m0;
            *(float4*)&ynext[n0 * 64 + c0] = o0;
            *(float4*)&ynext[(n0 + 1) * 64 + c0] = o1;
        }

        // ---- in-kernel pooling of h' (batch sorted: run-accumulate + flush) ----
        {
            int c = tid & 63, sg = tid >> 6;  // 4 groups x 8 rows
            float acc = 0.f;
            int curg = sbatch[sg * 8];
#pragma unroll
            for (int r = sg * 8; r < sg * 8 + 8; r++) {
                int g = sbatch[r];
                if (g != curg) {
                    atomicAdd(&g_pool[curg * 256 + loff + c], acc);
                    acc = 0.f;
                    curg = g;
                }
                acc += tsh[r * 68 + c];
            }
            atomicAdd(&g_pool[curg * 256 + loff + c], acc);
        }
    }
}

// ---------------- JK projection at graph granularity ----------------
__global__ void k_jk(const float* __restrict__ Wjk, const float* __restrict__ bjk) {
    int g = blockIdx.x;
    int c = threadIdx.x;  // 64
    float acc = (float)g_cnt[g] * bjk[c];
#pragma unroll 4
    for (int k = 0; k < 256; k++) acc += g_pool[g * 256 + k] * Wjk[k * 64 + c];
    g_pooledT[c * NG + g] = acc;
}

// ---------------- classifier: Linear -> BN(batch stats) -> ReLU -> Linear ----------------
__global__ __launch_bounds__(128) void k_final(const float* __restrict__ Wc1,
                                               const float* __restrict__ bc1,
                                               const float* __restrict__ gamma,
                                               const float* __restrict__ beta,
                                               const float* __restrict__ Wc2,
                                               const float* __restrict__ bc2,
                                               float* __restrict__ out) {
    extern __shared__ float sm[];
    float* Wc1s = sm;                  // 4096
    float* zsh = Wc1s + 4096;          // 128*66
    float* scv = zsh + 128 * 66;       // 64
    float* shv = scv + 64;             // 64
    int tid = threadIdx.x;  // = graph index g
    for (int i = tid; i < 4096; i += 128) Wc1s[i] = Wc1[i];
    __syncthreads();

    float4 acc4[16];
#pragma unroll
    for (int c = 0; c < 16; c++) acc4[c] = *(const float4*)&bc1[c * 4];
    for (int k = 0; k < 64; k++) {
        float pk = g_pooledT[k * NG + tid];
#pragma unroll
        for (int c = 0; c < 16; c++) {
            float4 w = *(const float4*)&Wc1s[k * 64 + c * 4];
            acc4[c].x += pk * w.x; acc4[c].y += pk * w.y;
            acc4[c].z += pk * w.z; acc4[c].w += pk * w.w;
        }
    }
#pragma unroll
    for (int c = 0; c < 16; c++) {
        zsh[tid * 66 + c * 4 + 0] = acc4[c].x;
        zsh[tid * 66 + c * 4 + 1] = acc4[c].y;
        zsh[tid * 66 + c * 4 + 2] = acc4[c].z;
        zsh[tid * 66 + c * 4 + 3] = acc4[c].w;
    }
    __syncthreads();

    if (tid < 64) {
        float s = 0.f, s2 = 0.f;
        for (int g = 0; g < 128; g++) {
            float v = zsh[g * 66 + tid];
            s += v;
            s2 += v * v;
        }
        float mu = s * (1.0f / 128.0f);
        float var = s2 * (1.0f / 128.0f) - mu * mu;
        float sc = gamma[tid] * rsqrtf(var + 1e-5f);
        scv[tid] = sc;
        shv[tid] = beta[tid] - mu * sc;
    }
    __syncthreads();

    float ao[10];
#pragma unroll
    for (int o = 0; o < 10; o++) ao[o] = bc2[o];
    for (int c = 0; c < 64; c++) {
        float v = fmaxf(zsh[tid * 66 + c] * scv[c] + shv[c], 0.0f);
#pragma unroll
        for (int o = 0; o < 10; o++) ao[o] += v * Wc2[c * 10 + o];
    }
#pragma unroll
    for (int o = 0; o < 10; o++) out[tid * 10 + o] = ao[o];
}

// ---------------- end-of-call zeroing (prepares NEXT call) ----------------
__global__ void k_zero_post() {
    int i = blockIdx.x * blockDim.x + threadIdx.x;
    int stride = gridDim.x * blockDim.x;
    for (int j = i; j < NN; j += stride) g_deg[j] = 0;
    for (int j = i; j < NG * 4 * HID; j += stride) g_pool[j] = 0.0f;
    for (int j = i; j < NG; j += stride) g_cnt[j] = 0;
    for (int j = i; j < NB; j += stride) g_lb[j] = 0ULL;
}

// ---------------- launch ----------------
extern "C" void kernel_launch(void* const* d_in, const int* in_sizes, int n_in,
                              void* d_out, int out_size) {
    const float* x    = (const float*)d_in[0];
    const int*   ei   = (const int*)d_in[1];
    const int*   batch= (const int*)d_in[2];
    const float* W1f  = (const float*)d_in[3];
    const float* b1f  = (const float*)d_in[4];
    const float* W2f  = (const float*)d_in[5];
    const float* b2f  = (const float*)d_in[6];
    const float* W1r  = (const float*)d_in[7];
    const float* b1r  = (const float*)d_in[8];
    const float* W2r  = (const float*)d_in[9];
    const float* b2r  = (const float*)d_in[10];
    const float* Wjk  = (const float*)d_in[11];
    const float* bjk  = (const float*)d_in[12];
    const float* Wc1  = (const float*)d_in[13];
    const float* bc1  = (const float*)d_in[14];
    const float* gamma= (const float*)d_in[15];
    const float* beta = (const float*)d_in[16];
    const float* Wc2  = (const float*)d_in[17];
    const float* bc2  = (const float*)d_in[18];
    float* out = (float*)d_out;

    float *h0p = 0, *h1p = 0;
    cudaGetSymbolAddress((void**)&h0p, g_h0);
    cudaGetSymbolAddress((void**)&h1p, g_h1);

    const size_t smp  = (size_t)(8192 + 32 * 132) * sizeof(float);
    const size_t sml  = (size_t)(4096 + 4096 + 128 + 2 * 32 * 68) * sizeof(float);
    const size_t smll = (size_t)(4096 + 128 + 2 * 32 * 68) * sizeof(float);
    const size_t smf  = (size_t)(4096 + 128 * 66 + 128) * sizeof(float);
    cudaFuncSetAttribute(k_pre_hist,     cudaFuncAttributeMaxDynamicSharedMemorySize, (int)smp);
    cudaFuncSetAttribute(k_layer<false>, cudaFuncAttributeMaxDynamicSharedMemorySize, (int)sml);
    cudaFuncSetAttribute(k_layer<true>,  cudaFuncAttributeMaxDynamicSharedMemorySize, (int)smll);
    cudaFuncSetAttribute(k_final,        cudaFuncAttributeMaxDynamicSharedMemorySize, (int)smf);

    // launch 0: dense pre-GEMM + degree histogram + graph counts
    k_pre_hist<<<592, 256, smp>>>(x, W1f, ei, batch, h0p);
    // launch 1-2: CSR
    k_scanlb<<<NB, 1024>>>();
    k_fill<<<(NE + 255) / 256, 256>>>(ei);

    // launch 3 (profiled slot): layer 0
    k_layer<false><<<592, 256, sml>>>(h0p, b1f, W2f, b2f, W1r, batch, h1p, 0);
    k_layer<false><<<592, 256, sml>>>(h1p, b1r, W2r, b2r, W1r + 4096, batch, h0p, 64);
    k_layer<false><<<592, 256, sml>>>(h0p, b1r + 64, W2r + 4096, b2r + 64, W1r + 2 * 4096, batch, h1p, 128);
    k_layer<true><<<888, 256, smll>>>(h1p, b1r + 128, W2r + 2 * 4096, b2r + 128, nullptr, batch, nullptr, 192);

    // graph-granularity tail
    k_jk<<<NG, 64>>>(Wjk, bjk);
    k_final<<<1, 128, smf>>>(Wc1, bc1, gamma, beta, Wc2, bc2, out);

    // zero accumulators for the NEXT call (after all readers above)
    k_zero_post<<<256, 256>>>();
}

// round 6
// speedup vs baseline: 1.6049x; 1.0655x over previous
#include <cuda_runtime.h>

#define NN 100000
#define NNP 100032   // padded to 64-row tiles
#define NE 1600000
#define NG 128
#define HID 64
#define NB 98        // ceil(NN / 1024)
#define NTILES 3125  // NN / 32  (pre_hist tiles)
#define LTILES 1563  // ceil(NN / 64) (layer tiles)

// ---------------- scratch (device globals: allocation-free) ----------------
// accumulated-into buffers (g_deg, g_pool, g_cnt, g_lb) are zeroed at the END
// of each kernel_launch (k_zero_post). Module-load zero-init covers call 1.
__device__ int   g_deg[NN];
__device__ int   g_rowptr[NN + 1];
__device__ int   g_cursor[NN];
__device__ int   g_col[NE];
__device__ unsigned long long g_lb[NB];  // lookback scan state (flag<<62 | value)
__device__ float g_h0[NNP * HID];
__device__ float g_h1[NNP * HID];
__device__ float g_pool[NG * 4 * HID];   // pooled per-layer h', [G][256]
__device__ int   g_cnt[NG];
__device__ float g_pooledT[HID * NG];    // JK output, transposed [c][g]

#define FMA4(acc, wv, sv) { (acc).x += (sv) * (wv).x; (acc).y += (sv) * (wv).y; \
                            (acc).z += (sv) * (wv).z; (acc).w += (sv) * (wv).w; }

// ---------------- launch 0: fused y0 = x @ W1f  +  deg histogram  +  graph counts ----
__global__ __launch_bounds__(256) void k_pre_hist(const float* __restrict__ x,
                                                  const float* __restrict__ W1f,
                                                  const int* __restrict__ ei,
                                                  const int* __restrict__ batch,
                                                  float* __restrict__ y0) {
    extern __shared__ float sm[];
    float* W1s = sm;          // 128*64 = 8192
    float* xs  = sm + 8192;   // 32*132
    int tid = threadIdx.x;
    for (int i = tid; i < 8192; i += 256) W1s[i] = W1f[i];
    // zero the pad rows of y0 (rows NN..NNP-1)
    if (blockIdx.x == 0) {
        for (int i = tid; i < (NNP - NN) * 64; i += 256) y0[NN * 64 + i] = 0.0f;
    }
    const int ty = tid >> 4, tx = tid & 15;
    const int m0 = ty * 2, c0 = tx * 4;
    const float4* __restrict__ x4 = (const float4*)x;

    for (int tile = blockIdx.x; tile < NTILES; tile += gridDim.x) {
        __syncthreads();
        // --- degree histogram: 512 edges per tile (3125*512 = NE exactly) ---
        {
            int e0 = tile * 512;
            int d0 = ei[NE + e0 + tid];
            int d1 = ei[NE + e0 + 256 + tid];
            atomicAdd(&g_deg[d0], 1);
            atomicAdd(&g_deg[d1], 1);
        }
        // --- nodes-per-graph counts (warp 0, batch sorted) ---
        if (tid < 32) {
            int g = batch[tile * 32 + tid];
            unsigned mask = __match_any_sync(0xffffffffu, g);
            if (tid == __ffs(mask) - 1) atomicAdd(&g_cnt[g], __popc(mask));
        }
        // --- load x tile [32 x 128] coalesced ---
#pragma unroll
        for (int i = 0; i < 4; i++) {
            int j = tid + i * 256;       // 0..1023
            int r = j >> 5, cv = j & 31;
            *(float4*)&xs[r * 132 + cv * 4] = x4[(tile * 32 + r) * 32 + cv];
        }
        __syncthreads();
        // --- y = x @ W1f (no bias/relu: folded into layer kernel) ---
        float4 a0 = make_float4(0.f, 0.f, 0.f, 0.f), a1 = a0;
#pragma unroll 8
        for (int k = 0; k < 128; k++) {
            float4 wv = *(const float4*)&W1s[k * 64 + c0];
            float z0 = xs[(m0 + 0) * 132 + k];
            float z1 = xs[(m0 + 1) * 132 + k];
            FMA4(a0, wv, z0);
            FMA4(a1, wv, z1);
        }
        int n0 = tile * 32 + m0;
        *(float4*)&y0[n0 * 64 + c0] = a0;
        *(float4*)&y0[(n0 + 1) * 64 + c0] = a1;
    }
}

// ---------------- single-pass decoupled-lookback exclusive scan ----------------
__global__ __launch_bounds__(1024) void k_scanlb() {
    __shared__ int s[1024];
    __shared__ int s_base;
    int t = threadIdx.x, b = blockIdx.x;
    int i = b * 1024 + t;
    int v = (i < NN) ? g_deg[i] : 0;
    s[t] = v;
    __syncthreads();
#pragma unroll
    for (int off = 1; off < 1024; off <<= 1) {
        int u = (t >= off) ? s[t - off] : 0;
        __syncthreads();
        s[t] += u;
        __syncthreads();
    }
    int agg = s[1023];
    if (t == 0) {
        if (b == 0) {
            atomicExch(&g_lb[0], (2ULL << 62) | (unsigned)agg);
            s_base = 0;
        } else {
            atomicExch(&g_lb[b], (1ULL << 62) | (unsigned)agg);
            int running = 0;
            int j = b - 1;
            while (true) {
                unsigned long long xx;
                do { xx = atomicAdd(&g_lb[j], 0ULL); } while ((xx >> 62) == 0);
                running += (int)(unsigned)(xx & 0xffffffffULL);
                if ((xx >> 62) == 2ULL) break;
                j--;
            }
            atomicExch(&g_lb[b], (2ULL << 62) | (unsigned)(running + agg));
            s_base = running;
        }
    }
    __syncthreads();
    if (i < NN) {
        int ex = s[t] - v + s_base;
        g_rowptr[i] = ex;
        g_cursor[i] = ex;
    }
    if (i == 0) g_rowptr[NN] = NE;
}

// fill CSR col (src indices) keyed by dst
__global__ void k_fill(const int* __restrict__ ei) {
    int e = blockIdx.x * blockDim.x + threadIdx.x;
    if (e < NE) {
        int d = ei[NE + e];
        int slot = atomicAdd(&g_cursor[d], 1);
        g_col[slot] = ei[e];
    }
}

// ---------------- fused GIN layer on pre-transformed features ----------------
// 64-node tiles, 256 threads, 4x4 register-tiled GEMMs with k-unroll-4.
//   t  = relu(y_self + agg(y) + b1)      (gather in 64-dim, half-warp rows)
//   h' = relu(t @ W2 + b2)
//   pool h' into g_pool (run-accumulated; pad rows excluded)
//   y_next = h' @ W1next                 (skipped when LAST)
template <bool LAST>
__global__ __launch_bounds__(256) void k_layer(const float* __restrict__ yin,
                                               const float* __restrict__ b1,
                                               const float* __restrict__ W2,
                                               const float* __restrict__ b2,
                                               const float* __restrict__ W1n,
                                               const int* __restrict__ batch,
                                               float* __restrict__ ynext,
                                               int loff) {
    constexpr int W1N_SZ = LAST ? 0 : 4096;
    extern __shared__ float sm[];
    float* W2s  = sm;                        // 4096
    float* W1ns = sm + 4096;                 // 4096 (absent when LAST)
    float* b1s  = sm + 4096 + W1N_SZ;        // 64
    float* b2s  = b1s + 64;                  // 64
    float* zsh  = b2s + 64;                  // 64*68  (holds t)
    float* tsh  = zsh + 64 * 68;             // 64*68  (holds h')
    __shared__ int sbatch[64];

    int tid = threadIdx.x;
    for (int i = tid; i < 4096; i += 256) W2s[i] = W2[i];
    if (!LAST) for (int i = tid; i < 4096; i += 256) W1ns[i] = W1n[i];
    if (tid < 64) { b1s[tid] = b1[tid]; b2s[tid] = b2[tid]; }

    const int warp = tid >> 5, lane = tid & 31;
    const int half = lane >> 4, l16 = lane & 15;
    const unsigned hm = 0xFFFFu << (half * 16);
    const int ty = tid >> 4, tx = tid & 15;
    const int m0 = ty * 4, c0 = tx * 4;
    const float4* __restrict__ yin4 = (const float4*)yin;

    for (int tile = blockIdx.x; tile < LTILES; tile += gridDim.x) {
        __syncthreads();  // protect zsh/tsh/sbatch from previous iteration's readers
        if (tid < 64) {
            int n = tile * 64 + tid;
            sbatch[tid] = (n < NN) ? batch[n] : 0;
        }

        // ---- gather: t = relu(y_self + agg(y) + b1), half-warp rows (8 rows/warp) ----
        {
            float4 bb = *(const float4*)&b1s[4 * l16];
#pragma unroll
            for (int s = 0; s < 4; s++) {
                int m = warp * 8 + s * 2 + half;
                int n = tile * 64 + m;
                if (n < NN) {
                    float4 acc = yin4[n * 16 + l16];  // self term
                    int rs = g_rowptr[n];
                    int re = g_rowptr[n + 1];
                    for (int j0 = rs; j0 < re; j0 += 16) {
                        int myc = (j0 + l16 < re) ? g_col[j0 + l16] : 0;
                        int cnt = min(16, re - j0);
                        int jj = 0;
                        for (; jj + 4 <= cnt; jj += 4) {
                            int s0 = __shfl_sync(hm, myc, jj, 16);
                            int s1 = __shfl_sync(hm, myc, jj + 1, 16);
                            int s2 = __shfl_sync(hm, myc, jj + 2, 16);
                            int s3 = __shfl_sync(hm, myc, jj + 3, 16);
                            float4 v0 = yin4[s0 * 16 + l16];
                            float4 v1 = yin4[s1 * 16 + l16];
                            float4 v2 = yin4[s2 * 16 + l16];
                            float4 v3 = yin4[s3 * 16 + l16];
                            acc.x += (v0.x + v1.x) + (v2.x + v3.x);
                            acc.y += (v0.y + v1.y) + (v2.y + v3.y);
                            acc.z += (v0.z + v1.z) + (v2.z + v3.z);
                            acc.w += (v0.w + v1.w) + (v2.w + v3.w);
                        }
                        for (; jj < cnt; jj++) {
                            int sj = __shfl_sync(hm, myc, jj, 16);
                            float4 v = yin4[sj * 16 + l16];
                            acc.x += v.x; acc.y += v.y; acc.z += v.z; acc.w += v.w;
                        }
                    }
                    acc.x = fmaxf(acc.x + bb.x, 0.f);
                    acc.y = fmaxf(acc.y + bb.y, 0.f);
                    acc.z = fmaxf(acc.z + bb.z, 0.f);
                    acc.w = fmaxf(acc.w + bb.w, 0.f);
                    *(float4*)&zsh[m * 68 + 4 * l16] = acc;
                } else {
                    *(float4*)&zsh[m * 68 + 4 * l16] = make_float4(0.f, 0.f, 0.f, 0.f);
                }
            }
        }
        __syncthreads();

        // ---- h' = relu(t @ W2 + b2) -> tsh   (4 rows x 4 cols, k-unroll 4) ----
        {
            float4 bb = *(const float4*)&b2s[c0];
            float4 a0 = bb, a1 = bb, a2 = bb, a3 = bb;
#pragma unroll
            for (int k = 0; k < 64; k += 4) {
                float4 z0 = *(const float4*)&zsh[(m0 + 0) * 68 + k];
                float4 z1 = *(const float4*)&zsh[(m0 + 1) * 68 + k];
                float4 z2 = *(const float4*)&zsh[(m0 + 2) * 68 + k];
                float4 z3 = *(const float4*)&zsh[(m0 + 3) * 68 + k];
                float4 u0 = *(const float4*)&W2s[(k + 0) * 64 + c0];
                float4 u1 = *(const float4*)&W2s[(k + 1) * 64 + c0];
                float4 u2 = *(const float4*)&W2s[(k + 2) * 64 + c0];
                float4 u3 = *(const float4*)&W2s[(k + 3) * 64 + c0];
                FMA4(a0, u0, z0.x); FMA4(a0, u1, z0.y); FMA4(a0, u2, z0.z); FMA4(a0, u3, z0.w);
                FMA4(a1, u0, z1.x); FMA4(a1, u1, z1.y); FMA4(a1, u2, z1.z); FMA4(a1, u3, z1.w);
                FMA4(a2, u0, z2.x); FMA4(a2, u1, z2.y); FMA4(a2, u2, z2.z); FMA4(a2, u3, z2.w);
                FMA4(a3, u0, z3.x); FMA4(a3, u1, z3.y); FMA4(a3, u2, z3.z); FMA4(a3, u3, z3.w);
            }
            a0.x = fmaxf(a0.x, 0.f); a0.y = fmaxf(a0.y, 0.f); a0.z = fmaxf(a0.z, 0.f); a0.w = fmaxf(a0.w, 0.f);
            a1.x = fmaxf(a1.x, 0.f); a1.y = fmaxf(a1.y, 0.f); a1.z = fmaxf(a1.z, 0.f); a1.w = fmaxf(a1.w, 0.f);
            a2.x = fmaxf(a2.x, 0.f); a2.y = fmaxf(a2.y, 0.f); a2.z = fmaxf(a2.z, 0.f); a2.w = fmaxf(a2.w, 0.f);
            a3.x = fmaxf(a3.x, 0.f); a3.y = fmaxf(a3.y, 0.f); a3.z = fmaxf(a3.z, 0.f); a3.w = fmaxf(a3.w, 0.f);
            *(float4*)&tsh[(m0 + 0) * 68 + c0] = a0;
            *(float4*)&tsh[(m0 + 1) * 68 + c0] = a1;
            *(float4*)&tsh[(m0 + 2) * 68 + c0] = a2;
            *(float4*)&tsh[(m0 + 3) * 68 + c0] = a3;
        }
        __syncthreads();

        // ---- y_next = h' @ W1next -> global (skipped on last layer) ----
        if (!LAST) {
            float4 a0 = make_float4(0.f, 0.f, 0.f, 0.f), a1 = a0, a2 = a0, a3 = a0;
#pragma unroll
            for (int k = 0; k < 64; k += 4) {
                float4 z0 = *(const float4*)&tsh[(m0 + 0) * 68 + k];
                float4 z1 = *(const float4*)&tsh[(m0 + 1) * 68 + k];
                float4 z2 = *(const float4*)&tsh[(m0 + 2) * 68 + k];
                float4 z3 = *(const float4*)&tsh[(m0 + 3) * 68 + k];
                float4 u0 = *(const float4*)&W1ns[(k + 0) * 64 + c0];
                float4 u1 = *(const float4*)&W1ns[(k + 1) * 64 + c0];
                float4 u2 = *(const float4*)&W1ns[(k + 2) * 64 + c0];
                float4 u3 = *(const float4*)&W1ns[(k + 3) * 64 + c0];
                FMA4(a0, u0, z0.x); FMA4(a0, u1, z0.y); FMA4(a0, u2, z0.z); FMA4(a0, u3, z0.w);
                FMA4(a1, u0, z1.x); FMA4(a1, u1, z1.y); FMA4(a1, u2, z1.z); FMA4(a1, u3, z1.w);
                FMA4(a2, u0, z2.x); FMA4(a2, u1, z2.y); FMA4(a2, u2, z2.z); FMA4(a2, u3, z2.w);
                FMA4(a3, u0, z3.x); FMA4(a3, u1, z3.y); FMA4(a3, u2, z3.z); FMA4(a3, u3, z3.w);
            }
            int n0 = tile * 64 + m0;
            *(float4*)&ynext[(n0 + 0) * 64 + c0] = a0;
            *(float4*)&ynext[(n0 + 1) * 64 + c0] = a1;
            *(float4*)&ynext[(n0 + 2) * 64 + c0] = a2;
            *(float4*)&ynext[(n0 + 3) * 64 + c0] = a3;
        }

        // ---- in-kernel pooling of h' (batch sorted: run-accumulate + flush) ----
        {
            int c = tid & 63, sg = tid >> 6;  // 4 groups x 16 rows
            float acc = 0.f;
            int curg = -1;
            for (int r = sg * 16; r < sg * 16 + 16; r++) {
                int n = tile * 64 + r;
                if (n >= NN) break;
                int g = sbatch[r];
                if (g != curg) {
                    if (curg >= 0) atomicAdd(&g_pool[curg * 256 + loff + c], acc);
                    acc = 0.f;
                    curg = g;
                }
                acc += tsh[r * 68 + c];
            }
            if (curg >= 0) atomicAdd(&g_pool[curg * 256 + loff + c], acc);
        }
    }
}

// ---------------- JK projection at graph granularity ----------------
__global__ void k_jk(const float* __restrict__ Wjk, const float* __restrict__ bjk) {
    int g = blockIdx.x;
    int c = threadIdx.x;  // 64
    float acc = (float)g_cnt[g] * bjk[c];
#pragma unroll 4
    for (int k = 0; k < 256; k++) acc += g_pool[g * 256 + k] * Wjk[k * 64 + c];
    g_pooledT[c * NG + g] = acc;
}

// ---------------- classifier: Linear -> BN(batch stats) -> ReLU -> Linear ----------------
__global__ __launch_bounds__(128) void k_final(const float* __restrict__ Wc1,
                                               const float* __restrict__ bc1,
                                               const float* __restrict__ gamma,
                                               const float* __restrict__ beta,
                                               const float* __restrict__ Wc2,
                                               const float* __restrict__ bc2,
                                               float* __restrict__ out) {
    extern __shared__ float sm[];
    float* Wc1s = sm;                  // 4096
    float* zsh = Wc1s + 4096;          // 128*66
    float* scv = zsh + 128 * 66;       // 64
    float* shv = scv + 64;             // 64
    int tid = threadIdx.x;  // = graph index g
    for (int i = tid; i < 4096; i += 128) Wc1s[i] = Wc1[i];
    __syncthreads();

    float4 acc4[16];
#pragma unroll
    for (int c = 0; c < 16; c++) acc4[c] = *(const float4*)&bc1[c * 4];
    for (int k = 0; k < 64; k++) {
        float pk = g_pooledT[k * NG + tid];
#pragma unroll
        for (int c = 0; c < 16; c++) {
            float4 wv = *(const float4*)&Wc1s[k * 64 + c * 4];
            acc4[c].x += pk * wv.x; acc4[c].y += pk * wv.y;
            acc4[c].z += pk * wv.z; acc4[c].w += pk * wv.w;
        }
    }
#pragma unroll
    for (int c = 0; c < 16; c++) {
        zsh[tid * 66 + c * 4 + 0] = acc4[c].x;
        zsh[tid * 66 + c * 4 + 1] = acc4[c].y;
        zsh[tid * 66 + c * 4 + 2] = acc4[c].z;
        zsh[tid * 66 + c * 4 + 3] = acc4[c].w;
    }
    __syncthreads();

    if (tid < 64) {
        float s = 0.f, s2 = 0.f;
        for (int g = 0; g < 128; g++) {
            float v = zsh[g * 66 + tid];
            s += v;
            s2 += v * v;
        }
        float mu = s * (1.0f / 128.0f);
        float var = s2 * (1.0f / 128.0f) - mu * mu;
        float sc = gamma[tid] * rsqrtf(var + 1e-5f);
        scv[tid] = sc;
        shv[tid] = beta[tid] - mu * sc;
    }
    __syncthreads();

    float ao[10];
#pragma unroll
    for (int o = 0; o < 10; o++) ao[o] = bc2[o];
    for (int c = 0; c < 64; c++) {
        float v = fmaxf(zsh[tid * 66 + c] * scv[c] + shv[c], 0.0f);
#pragma unroll
        for (int o = 0; o < 10; o++) ao[o] += v * Wc2[c * 10 + o];
    }
#pragma unroll
    for (int o = 0; o < 10; o++) out[tid * 10 + o] = ao[o];
}

// ---------------- end-of-call zeroing (prepares NEXT call) ----------------
__global__ void k_zero_post() {
    int i = blockIdx.x * blockDim.x + threadIdx.x;
    int stride = gridDim.x * blockDim.x;
    for (int j = i; j < NN; j += stride) g_deg[j] = 0;
    for (int j = i; j < NG * 4 * HID; j += stride) g_pool[j] = 0.0f;
    for (int j = i; j < NG; j += stride) g_cnt[j] = 0;
    for (int j = i; j < NB; j += stride) g_lb[j] = 0ULL;
}

// ---------------- launch ----------------
extern "C" void kernel_launch(void* const* d_in, const int* in_sizes, int n_in,
                              void* d_out, int out_size) {
    const float* x    = (const float*)d_in[0];
    const int*   ei   = (const int*)d_in[1];
    const int*   batch= (const int*)d_in[2];
    const float* W1f  = (const float*)d_in[3];
    const float* b1f  = (const float*)d_in[4];
    const float* W2f  = (const float*)d_in[5];
    const float* b2f  = (const float*)d_in[6];
    const float* W1r  = (const float*)d_in[7];
    const float* b1r  = (const float*)d_in[8];
    const float* W2r  = (const float*)d_in[9];
    const float* b2r  = (const float*)d_in[10];
    const float* Wjk  = (const float*)d_in[11];
    const float* bjk  = (const float*)d_in[12];
    const float* Wc1  = (const float*)d_in[13];
    const float* bc1  = (const float*)d_in[14];
    const float* gamma= (const float*)d_in[15];
    const float* beta = (const float*)d_in[16];
    const float* Wc2  = (const float*)d_in[17];
    const float* bc2  = (const float*)d_in[18];
    float* out = (float*)d_out;

    float *h0p = 0, *h1p = 0;
    cudaGetSymbolAddress((void**)&h0p, g_h0);
    cudaGetSymbolAddress((void**)&h1p, g_h1);

    const size_t smp  = (size_t)(8192 + 32 * 132) * sizeof(float);
    const size_t sml  = (size_t)(4096 + 4096 + 128 + 2 * 64 * 68) * sizeof(float);
    const size_t smll = (size_t)(4096 + 128 + 2 * 64 * 68) * sizeof(float);
    const size_t smf  = (size_t)(4096 + 128 * 66 + 128) * sizeof(float);
    cudaFuncSetAttribute(k_pre_hist,     cudaFuncAttributeMaxDynamicSharedMemorySize, (int)smp);
    cudaFuncSetAttribute(k_layer<false>, cudaFuncAttributeMaxDynamicSharedMemorySize, (int)sml);
    cudaFuncSetAttribute(k_layer<true>,  cudaFuncAttributeMaxDynamicSharedMemorySize, (int)smll);
    cudaFuncSetAttribute(k_final,        cudaFuncAttributeMaxDynamicSharedMemorySize, (int)smf);

    // launch 0: dense pre-GEMM + degree histogram + graph counts (+ pad zeroing)
    k_pre_hist<<<592, 256, smp>>>(x, W1f, ei, batch, h0p);
    // launch 1-2: CSR
    k_scanlb<<<NB, 1024>>>();
    k_fill<<<(NE + 255) / 256, 256>>>(ei);

    // launch 3 (profiled slot): layer 0
    k_layer<false><<<444, 256, sml>>>(h0p, b1f, W2f, b2f, W1r, batch, h1p, 0);
    k_layer<false><<<444, 256, sml>>>(h1p, b1r, W2r, b2r, W1r + 4096, batch, h0p, 64);
    k_layer<false><<<444, 256, sml>>>(h0p, b1r + 64, W2r + 4096, b2r + 64, W1r + 2 * 4096, batch, h1p, 128);
    k_layer<true><<<592, 256, smll>>>(h1p, b1r + 128, W2r + 2 * 4096, b2r + 128, nullptr, batch, nullptr, 192);

    // graph-granularity tail
    k_jk<<<NG, 64>>>(Wjk, bjk);
    k_final<<<1, 128, smf>>>(Wc1, bc1, gamma, beta, Wc2, bc2, out);

    // zero accumulators for the NEXT call (after all readers above)
    k_zero_post<<<256, 256>>>();
}